// round 1
// baseline (speedup 1.0000x reference)
#include <cuda_runtime.h>
#include <cuda_bf16.h>

// ---------------- problem constants ----------------
#define B_    4
#define L_    4096
#define DM_   1024
#define H_    16
#define D_    64
#define M_    128
#define BH_   64          // B*H
#define SEG_  32          // L/M
#define NTOK_ 16384       // B*L

// ---------------- scratch (device globals; no allocations allowed) ----------------
__device__ float g_q [BH_ * L_ * D_];          // [bh][l][d]
__device__ float g_k [BH_ * L_ * D_];
__device__ float g_v [BH_ * L_ * D_];
__device__ float g_Ql[BH_ * M_ * D_];          // [bh][m][d]
__device__ float g_Kl[BH_ * M_ * D_];
__device__ float g_k1[(size_t)BH_ * L_ * M_];  // [bh][l][m]   softmaxed
__device__ float g_k3[(size_t)BH_ * M_ * L_];  // [bh][m][l]   raw then softmaxed in place
__device__ float g_k2[BH_ * M_ * M_];          // [bh][n][m]   softmaxed
__device__ float g_P [BH_ * M_ * M_];
__device__ float g_M1[BH_ * M_ * M_];
__device__ float g_M2[BH_ * M_ * M_];
__device__ float g_Va[BH_ * M_ * M_];
__device__ float g_Vb[BH_ * M_ * M_];
__device__ float g_k3v_part[8 * BH_ * M_ * D_];
__device__ float g_k3v[BH_ * M_ * D_];         // [bh][m][d]
__device__ float g_y2 [BH_ * M_ * D_];         // [bh][m][d]
__device__ float g_x  [(size_t)NTOK_ * DM_];   // [b*l][1024]

// =====================================================================
// SGEMM: C[16384,1024] = A[16384,1024] @ W[1024,1024] + bias
// 128x128 block tile, BK=16, 8x8 micro-tile, inner product via fma.rn.f32x2.
// mode 0/1/2: write to g_q/g_k/g_v in [bh][l][d] layout. mode 3: plain row-major
// to outp (A is taken from g_x in mode 3).
// =====================================================================
__global__ __launch_bounds__(256) void sgemm_kernel(
    const float* __restrict__ Ain, const float* __restrict__ W,
    const float* __restrict__ bias, float* __restrict__ outp, int mode)
{
    __shared__ __align__(16) float As[16][128];
    __shared__ __align__(16) float Bs[16][128];

    const float* A = (mode == 3) ? (const float*)g_x : Ain;
    const int m0 = blockIdx.y * 128;
    const int n0 = blockIdx.x * 128;
    const int tid = threadIdx.x;
    const int ar = tid >> 2, ac = (tid & 3) << 2;   // A tile load: 64 rows x 16 cols (x2 passes)
    const int br = tid >> 4, bc = (tid & 15) << 2;  // B tile load: 16 rows x 64 cols (x2 passes)
    const int tm = tid >> 4, tn = tid & 15;

    unsigned long long acc[8][4];
    #pragma unroll
    for (int i = 0; i < 8; i++)
        #pragma unroll
        for (int j = 0; j < 4; j++) acc[i][j] = 0ull;

    for (int k0 = 0; k0 < 1024; k0 += 16) {
        float4 a0 = *(const float4*)&A[(size_t)(m0 + ar) * 1024 + k0 + ac];
        float4 a1 = *(const float4*)&A[(size_t)(m0 + ar + 64) * 1024 + k0 + ac];
        float4 b0 = *(const float4*)&W[(size_t)(k0 + br) * 1024 + n0 + bc];
        float4 b1 = *(const float4*)&W[(size_t)(k0 + br) * 1024 + n0 + bc + 64];
        __syncthreads();
        As[ac + 0][ar] = a0.x; As[ac + 1][ar] = a0.y; As[ac + 2][ar] = a0.z; As[ac + 3][ar] = a0.w;
        As[ac + 0][ar + 64] = a1.x; As[ac + 1][ar + 64] = a1.y;
        As[ac + 2][ar + 64] = a1.z; As[ac + 3][ar + 64] = a1.w;
        *(float4*)&Bs[br][bc]      = b0;
        *(float4*)&Bs[br][bc + 64] = b1;
        __syncthreads();

        #pragma unroll
        for (int kk = 0; kk < 16; kk++) {
            float4 av0 = *(const float4*)&As[kk][tm * 8];
            float4 av1 = *(const float4*)&As[kk][tm * 8 + 4];
            ulonglong2 bv0 = *(const ulonglong2*)&Bs[kk][tn * 8];
            ulonglong2 bv1 = *(const ulonglong2*)&Bs[kk][tn * 8 + 4];
            unsigned long long bb0 = bv0.x, bb1 = bv0.y, bb2 = bv1.x, bb3 = bv1.y;
            float aa[8] = {av0.x, av0.y, av0.z, av0.w, av1.x, av1.y, av1.z, av1.w};
            #pragma unroll
            for (int i = 0; i < 8; i++) {
                unsigned int au = __float_as_uint(aa[i]);
                unsigned long long a2;
                asm("mov.b64 %0,{%1,%1};" : "=l"(a2) : "r"(au));
                asm("fma.rn.f32x2 %0,%1,%2,%0;" : "+l"(acc[i][0]) : "l"(a2), "l"(bb0));
                asm("fma.rn.f32x2 %0,%1,%2,%0;" : "+l"(acc[i][1]) : "l"(a2), "l"(bb1));
                asm("fma.rn.f32x2 %0,%1,%2,%0;" : "+l"(acc[i][2]) : "l"(a2), "l"(bb2));
                asm("fma.rn.f32x2 %0,%1,%2,%0;" : "+l"(acc[i][3]) : "l"(a2), "l"(bb3));
            }
        }
    }

    #pragma unroll
    for (int i = 0; i < 8; i++) {
        int r = m0 + tm * 8 + i;
        #pragma unroll
        for (int j = 0; j < 4; j++) {
            int c = n0 + tn * 8 + j * 2;
            float lo = __uint_as_float((unsigned)(acc[i][j] & 0xffffffffull)) + bias[c];
            float hi = __uint_as_float((unsigned)(acc[i][j] >> 32)) + bias[c + 1];
            if (mode == 3) {
                outp[(size_t)r * 1024 + c]     = lo;
                outp[(size_t)r * 1024 + c + 1] = hi;
            } else {
                float* dst = (mode == 0) ? g_q : ((mode == 1) ? g_k : g_v);
                int b = r >> 12, l = r & 4095;
                int h = c >> 6,  d = c & 63;   // c even -> pair never crosses head boundary
                size_t o = (((size_t)(b * 16 + h) * 4096) + l) * 64 + d;
                dst[o]     = lo;
                dst[o + 1] = hi;
            }
        }
    }
}

// =====================================================================
// landmark pooling: mean over 32-token segments of q and k
// =====================================================================
__global__ void pool_kernel()
{
    int idx = blockIdx.x * blockDim.x + threadIdx.x;   // BH*M*D = 524288
    int d  = idx & 63;
    int m  = (idx >> 6) & 127;
    int bh = idx >> 13;
    size_t base = ((size_t)bh * L_ + m * SEG_) * D_ + d;
    float sq = 0.f, sk = 0.f;
    #pragma unroll
    for (int s = 0; s < SEG_; s++) { sq += g_q[base + s * D_]; sk += g_k[base + s * D_]; }
    g_Ql[idx] = sq * (1.f / SEG_);
    g_Kl[idx] = sk * (1.f / SEG_);
}

// =====================================================================
// kernel_1 = softmax(q @ K_l^T) fused (rows of 128) -> g_k1
// block: (l-chunk of 32, bh). dyn smem = 57344 B
// =====================================================================
__global__ __launch_bounds__(256) void k1_kernel()
{
    extern __shared__ float sm[];
    float* Klt = sm;                 // [d=64][m=128]
    float* Qt  = sm + 8192;          // [d=64][r=32]
    float* S   = sm + 8192 + 2048;   // [r=32][m=128]
    int bh = blockIdx.y, l0 = blockIdx.x * 32, tid = threadIdx.x;

    const float* Kl = g_Kl + bh * 8192;
    #pragma unroll
    for (int i = 0; i < 8; i++) {
        int f = i * 1024 + tid * 4; int m = f >> 6, d0 = f & 63;
        float4 t = *(const float4*)&Kl[f];
        Klt[(d0 + 0) * 128 + m] = t.x; Klt[(d0 + 1) * 128 + m] = t.y;
        Klt[(d0 + 2) * 128 + m] = t.z; Klt[(d0 + 3) * 128 + m] = t.w;
    }
    const float* qp = g_q + ((size_t)bh * L_ + l0) * D_;
    #pragma unroll
    for (int i = 0; i < 2; i++) {
        int f = i * 1024 + tid * 4; int r = f >> 6, d0 = f & 63;
        float4 t = *(const float4*)&qp[f];
        Qt[(d0 + 0) * 32 + r] = t.x; Qt[(d0 + 1) * 32 + r] = t.y;
        Qt[(d0 + 2) * 32 + r] = t.z; Qt[(d0 + 3) * 32 + r] = t.w;
    }
    __syncthreads();

    int rb = (tid >> 5) * 4, cb = (tid & 31) * 4;
    float acc[4][4] = {};
    for (int d = 0; d < 64; d++) {
        float a0 = Qt[d * 32 + rb + 0], a1 = Qt[d * 32 + rb + 1];
        float a2 = Qt[d * 32 + rb + 2], a3 = Qt[d * 32 + rb + 3];
        float4 b = *(const float4*)&Klt[d * 128 + cb];
        acc[0][0] += a0 * b.x; acc[0][1] += a0 * b.y; acc[0][2] += a0 * b.z; acc[0][3] += a0 * b.w;
        acc[1][0] += a1 * b.x; acc[1][1] += a1 * b.y; acc[1][2] += a1 * b.z; acc[1][3] += a1 * b.w;
        acc[2][0] += a2 * b.x; acc[2][1] += a2 * b.y; acc[2][2] += a2 * b.z; acc[2][3] += a2 * b.w;
        acc[3][0] += a3 * b.x; acc[3][1] += a3 * b.y; acc[3][2] += a3 * b.z; acc[3][3] += a3 * b.w;
    }
    #pragma unroll
    for (int i = 0; i < 4; i++)
        #pragma unroll
        for (int j = 0; j < 4; j++) S[(rb + i) * 128 + cb + j] = acc[i][j];
    __syncthreads();

    int lane = tid & 31, w = tid >> 5;
    for (int rr = 0; rr < 4; rr++) {
        int row = w * 4 + rr;
        float x0 = S[row * 128 + lane],      x1 = S[row * 128 + lane + 32];
        float x2 = S[row * 128 + lane + 64], x3 = S[row * 128 + lane + 96];
        float mx = fmaxf(fmaxf(x0, x1), fmaxf(x2, x3));
        #pragma unroll
        for (int o = 16; o; o >>= 1) mx = fmaxf(mx, __shfl_xor_sync(0xffffffffu, mx, o));
        float e0 = __expf(x0 - mx), e1 = __expf(x1 - mx);
        float e2 = __expf(x2 - mx), e3 = __expf(x3 - mx);
        float s = e0 + e1 + e2 + e3;
        #pragma unroll
        for (int o = 16; o; o >>= 1) s += __shfl_xor_sync(0xffffffffu, s, o);
        float inv = 1.f / s;
        float* o = g_k1 + (size_t)bh * (M_ * L_) + (size_t)(l0 + row) * 128;
        o[lane] = e0 * inv; o[lane + 32] = e1 * inv; o[lane + 64] = e2 * inv; o[lane + 96] = e3 * inv;
    }
}

// =====================================================================
// kernel_3 raw scores: S[m][l] = Q_l[m] . k[l]  -> g_k3 (raw)
// block: (l-chunk of 128, bh). dyn smem = 65536 B
// =====================================================================
__global__ __launch_bounds__(256) void k3score_kernel()
{
    extern __shared__ float sm[];
    float* Qlt = sm;          // [d][m]
    float* Kt  = sm + 8192;   // [d][l]
    int bh = blockIdx.y, l0 = blockIdx.x * 128, tid = threadIdx.x;

    const float* Ql = g_Ql + bh * 8192;
    #pragma unroll
    for (int i = 0; i < 8; i++) {
        int f = i * 1024 + tid * 4; int m = f >> 6, d0 = f & 63;
        float4 t = *(const float4*)&Ql[f];
        Qlt[(d0 + 0) * 128 + m] = t.x; Qlt[(d0 + 1) * 128 + m] = t.y;
        Qlt[(d0 + 2) * 128 + m] = t.z; Qlt[(d0 + 3) * 128 + m] = t.w;
    }
    const float* kp = g_k + ((size_t)bh * L_ + l0) * D_;
    #pragma unroll
    for (int i = 0; i < 8; i++) {
        int f = i * 1024 + tid * 4; int r = f >> 6, d0 = f & 63;
        float4 t = *(const float4*)&kp[f];
        Kt[(d0 + 0) * 128 + r] = t.x; Kt[(d0 + 1) * 128 + r] = t.y;
        Kt[(d0 + 2) * 128 + r] = t.z; Kt[(d0 + 3) * 128 + r] = t.w;
    }
    __syncthreads();

    int tm = tid >> 4, tn = tid & 15;
    float acc[8][8] = {};
    for (int d = 0; d < 64; d++) {
        float4 a0 = *(const float4*)&Qlt[d * 128 + tm * 8];
        float4 a1 = *(const float4*)&Qlt[d * 128 + tm * 8 + 4];
        float4 b0 = *(const float4*)&Kt[d * 128 + tn * 8];
        float4 b1 = *(const float4*)&Kt[d * 128 + tn * 8 + 4];
        float av[8] = {a0.x, a0.y, a0.z, a0.w, a1.x, a1.y, a1.z, a1.w};
        float bv[8] = {b0.x, b0.y, b0.z, b0.w, b1.x, b1.y, b1.z, b1.w};
        #pragma unroll
        for (int i = 0; i < 8; i++)
            #pragma unroll
            for (int j = 0; j < 8; j++) acc[i][j] += av[i] * bv[j];
    }
    float* o = g_k3 + (size_t)bh * (M_ * L_);
    #pragma unroll
    for (int i = 0; i < 8; i++) {
        size_t base = (size_t)(tm * 8 + i) * L_ + l0 + tn * 8;
        float4 v0 = make_float4(acc[i][0], acc[i][1], acc[i][2], acc[i][3]);
        float4 v1 = make_float4(acc[i][4], acc[i][5], acc[i][6], acc[i][7]);
        *(float4*)&o[base] = v0; *(float4*)&o[base + 4] = v1;
    }
}

// =====================================================================
// row softmax over 4096 (in place on g_k3). block per row (8192 blocks).
// =====================================================================
__global__ __launch_bounds__(256) void softmax4096_kernel()
{
    size_t row = blockIdx.x;
    float* p = g_k3 + row * 4096;
    int tid = threadIdx.x;
    float v[16];
    float mx = -1e30f;
    #pragma unroll
    for (int i = 0; i < 4; i++) {
        float4 t = *(const float4*)&p[i * 1024 + tid * 4];
        v[i * 4 + 0] = t.x; v[i * 4 + 1] = t.y; v[i * 4 + 2] = t.z; v[i * 4 + 3] = t.w;
        mx = fmaxf(mx, fmaxf(fmaxf(t.x, t.y), fmaxf(t.z, t.w)));
    }
    __shared__ float smx[8], ssm[8], sres;
    #pragma unroll
    for (int o = 16; o; o >>= 1) mx = fmaxf(mx, __shfl_xor_sync(0xffffffffu, mx, o));
    if ((tid & 31) == 0) smx[tid >> 5] = mx;
    __syncthreads();
    if (tid == 0) {
        float m = smx[0];
        #pragma unroll
        for (int i = 1; i < 8; i++) m = fmaxf(m, smx[i]);
        sres = m;
    }
    __syncthreads();
    float MX = sres;
    float s = 0.f;
    #pragma unroll
    for (int i = 0; i < 16; i++) { v[i] = __expf(v[i] - MX); s += v[i]; }
    #pragma unroll
    for (int o = 16; o; o >>= 1) s += __shfl_xor_sync(0xffffffffu, s, o);
    if ((tid & 31) == 0) ssm[tid >> 5] = s;
    __syncthreads();
    if (tid == 0) {
        float t = 0.f;
        #pragma unroll
        for (int i = 0; i < 8; i++) t += ssm[i];
        sres = 1.f / t;
    }
    __syncthreads();
    float inv = sres;
    #pragma unroll
    for (int i = 0; i < 4; i++) {
        float4 t = make_float4(v[i*4]*inv, v[i*4+1]*inv, v[i*4+2]*inv, v[i*4+3]*inv);
        *(float4*)&p[i * 1024 + tid * 4] = t;
    }
}

// =====================================================================
// kernel_2 = softmax(Q_l @ K_l^T) fused. block per head. dyn smem 131072 B
// =====================================================================
__global__ __launch_bounds__(256) void k2_kernel()
{
    extern __shared__ float sm[];
    float* Qlt = sm;            // [d][n]
    float* Klt = sm + 8192;     // [d][m]
    float* S   = sm + 16384;    // [n][m]
    int bh = blockIdx.x, tid = threadIdx.x;

    const float* Ql = g_Ql + bh * 8192;
    const float* Kl = g_Kl + bh * 8192;
    #pragma unroll
    for (int i = 0; i < 8; i++) {
        int f = i * 1024 + tid * 4; int m = f >> 6, d0 = f & 63;
        float4 tq = *(const float4*)&Ql[f];
        float4 tk = *(const float4*)&Kl[f];
        Qlt[(d0 + 0) * 128 + m] = tq.x; Qlt[(d0 + 1) * 128 + m] = tq.y;
        Qlt[(d0 + 2) * 128 + m] = tq.z; Qlt[(d0 + 3) * 128 + m] = tq.w;
        Klt[(d0 + 0) * 128 + m] = tk.x; Klt[(d0 + 1) * 128 + m] = tk.y;
        Klt[(d0 + 2) * 128 + m] = tk.z; Klt[(d0 + 3) * 128 + m] = tk.w;
    }
    __syncthreads();

    int tm = tid >> 4, tn = tid & 15;
    float acc[8][8] = {};
    for (int d = 0; d < 64; d++) {
        float4 a0 = *(const float4*)&Qlt[d * 128 + tm * 8];
        float4 a1 = *(const float4*)&Qlt[d * 128 + tm * 8 + 4];
        float4 b0 = *(const float4*)&Klt[d * 128 + tn * 8];
        float4 b1 = *(const float4*)&Klt[d * 128 + tn * 8 + 4];
        float av[8] = {a0.x, a0.y, a0.z, a0.w, a1.x, a1.y, a1.z, a1.w};
        float bv[8] = {b0.x, b0.y, b0.z, b0.w, b1.x, b1.y, b1.z, b1.w};
        #pragma unroll
        for (int i = 0; i < 8; i++)
            #pragma unroll
            for (int j = 0; j < 8; j++) acc[i][j] += av[i] * bv[j];
    }
    #pragma unroll
    for (int i = 0; i < 8; i++)
        #pragma unroll
        for (int j = 0; j < 8; j++) S[(tm * 8 + i) * 128 + tn * 8 + j] = acc[i][j];
    __syncthreads();

    int lane = tid & 31, w = tid >> 5;
    for (int rr = 0; rr < 16; rr++) {
        int row = w * 16 + rr;
        float x0 = S[row * 128 + lane],      x1 = S[row * 128 + lane + 32];
        float x2 = S[row * 128 + lane + 64], x3 = S[row * 128 + lane + 96];
        float mx = fmaxf(fmaxf(x0, x1), fmaxf(x2, x3));
        #pragma unroll
        for (int o = 16; o; o >>= 1) mx = fmaxf(mx, __shfl_xor_sync(0xffffffffu, mx, o));
        float e0 = __expf(x0 - mx), e1 = __expf(x1 - mx);
        float e2 = __expf(x2 - mx), e3 = __expf(x3 - mx);
        float s = e0 + e1 + e2 + e3;
        #pragma unroll
        for (int o = 16; o; o >>= 1) s += __shfl_xor_sync(0xffffffffu, s, o);
        float inv = 1.f / s;
        float* o = g_k2 + bh * 16384 + row * 128;
        o[lane] = e0 * inv; o[lane + 32] = e1 * inv; o[lane + 64] = e2 * inv; o[lane + 96] = e3 * inv;
    }
}

// =====================================================================
// V0 = K^T / max(colsum(K)). block per head.
// =====================================================================
__global__ __launch_bounds__(256) void vinit_kernel()
{
    int bh = blockIdx.x, tid = threadIdx.x;
    const float* K = g_k2 + bh * 16384;
    __shared__ float cs[128];
    __shared__ float sscale;
    if (tid < 128) {
        float s = 0.f;
        for (int r = 0; r < 128; r++) s += K[r * 128 + tid];
        cs[tid] = s;
    }
    __syncthreads();
    if (tid == 0) {
        float m = cs[0];
        for (int i = 1; i < 128; i++) m = fmaxf(m, cs[i]);
        sscale = 1.f / m;
    }
    __syncthreads();
    float scale = sscale;
    for (int f = tid; f < 16384; f += 256) {
        int i = f >> 7, j = f & 127;
        g_Va[bh * 16384 + f] = scale * K[j * 128 + i];
    }
}

// =====================================================================
// batched 128x128 bmm for Newton-Schulz: OUT = alpha*(A@B) + beta*C
// grid (4, 64): 32 output rows per block. dyn smem 81920 B
// buffer selectors: 0=g_k2 1=g_P 2=g_M1 3=g_M2 4=g_Va 5=g_Vb
// =====================================================================
__device__ __forceinline__ float* bufsel(int s)
{
    switch (s) {
        case 0: return g_k2; case 1: return g_P; case 2: return g_M1;
        case 3: return g_M2; case 4: return g_Va; default: return g_Vb;
    }
}

__global__ __launch_bounds__(256) void bmm_kernel(int as, int bs, int cs2, int os,
                                                  float alpha, float beta)
{
    extern __shared__ float sm[];
    float* Bs = sm;            // [k=128][c=128]
    float* At = sm + 16384;    // [k=128][r=32]
    int bh = blockIdx.y, r0 = blockIdx.x * 32, tid = threadIdx.x;
    const float* A  = bufsel(as)  + bh * 16384;
    const float* Bm = bufsel(bs)  + bh * 16384;
    const float* C  = bufsel(cs2) + bh * 16384;
    float* O        = bufsel(os)  + bh * 16384;

    #pragma unroll
    for (int i = 0; i < 16; i++) {
        int f = i * 1024 + tid * 4;
        *(float4*)&Bs[f] = *(const float4*)&Bm[f];
    }
    #pragma unroll
    for (int i = 0; i < 4; i++) {
        int f = i * 1024 + tid * 4; int r = f >> 7, k0 = f & 127;
        float4 t = *(const float4*)&A[(r0 + r) * 128 + k0];
        At[(k0 + 0) * 32 + r] = t.x; At[(k0 + 1) * 32 + r] = t.y;
        At[(k0 + 2) * 32 + r] = t.z; At[(k0 + 3) * 32 + r] = t.w;
    }
    __syncthreads();

    int rb = (tid >> 5) * 4, cb = (tid & 31) * 4;
    float acc[4][4] = {};
    for (int k = 0; k < 128; k++) {
        float a0 = At[k * 32 + rb + 0], a1 = At[k * 32 + rb + 1];
        float a2 = At[k * 32 + rb + 2], a3 = At[k * 32 + rb + 3];
        float4 b = *(const float4*)&Bs[k * 128 + cb];
        acc[0][0] += a0 * b.x; acc[0][1] += a0 * b.y; acc[0][2] += a0 * b.z; acc[0][3] += a0 * b.w;
        acc[1][0] += a1 * b.x; acc[1][1] += a1 * b.y; acc[1][2] += a1 * b.z; acc[1][3] += a1 * b.w;
        acc[2][0] += a2 * b.x; acc[2][1] += a2 * b.y; acc[2][2] += a2 * b.z; acc[2][3] += a2 * b.w;
        acc[3][0] += a3 * b.x; acc[3][1] += a3 * b.y; acc[3][2] += a3 * b.z; acc[3][3] += a3 * b.w;
    }
    #pragma unroll
    for (int i = 0; i < 4; i++)
        #pragma unroll
        for (int j = 0; j < 4; j++) {
            int idx = (r0 + rb + i) * 128 + cb + j;
            O[idx] = alpha * acc[i][j] + beta * C[idx];
        }
}

// =====================================================================
// k3v partial: (kernel_3 @ v) split-K(8). grid (8, 64). smem 24576 B
// =====================================================================
__global__ __launch_bounds__(256) void k3v_kernel()
{
    extern __shared__ float sm[];
    float* At = sm;           // [k=32][m=128]
    float* Vs = sm + 4096;    // [k=32][d=64]
    int s = blockIdx.x, bh = blockIdx.y, tid = threadIdx.x;
    int kbase = s * 512;
    int rt = tid >> 4, ct = tid & 15;
    float acc[8][4] = {};

    for (int kt = 0; kt < 512; kt += 32) {
        __syncthreads();
        #pragma unroll
        for (int i = 0; i < 4; i++) {
            int f = i * 1024 + tid * 4; int m = f >> 5, kk = f & 31;
            float4 t = *(const float4*)&g_k3[(size_t)bh * (M_ * L_) + (size_t)m * L_ + kbase + kt + kk];
            At[(kk + 0) * 128 + m] = t.x; At[(kk + 1) * 128 + m] = t.y;
            At[(kk + 2) * 128 + m] = t.z; At[(kk + 3) * 128 + m] = t.w;
        }
        #pragma unroll
        for (int i = 0; i < 2; i++) {
            int f = i * 1024 + tid * 4; int kk = f >> 6, d0 = f & 63;
            *(float4*)&Vs[kk * 64 + d0] =
                *(const float4*)&g_v[((size_t)bh * L_ + kbase + kt + kk) * D_ + d0];
        }
        __syncthreads();
        for (int k = 0; k < 32; k++) {
            float4 a0 = *(const float4*)&At[k * 128 + rt * 8];
            float4 a1 = *(const float4*)&At[k * 128 + rt * 8 + 4];
            float4 b  = *(const float4*)&Vs[k * 64 + ct * 4];
            float av[8] = {a0.x, a0.y, a0.z, a0.w, a1.x, a1.y, a1.z, a1.w};
            #pragma unroll
            for (int i = 0; i < 8; i++) {
                acc[i][0] += av[i] * b.x; acc[i][1] += av[i] * b.y;
                acc[i][2] += av[i] * b.z; acc[i][3] += av[i] * b.w;
            }
        }
    }
    #pragma unroll
    for (int i = 0; i < 8; i++) {
        float4 t = make_float4(acc[i][0], acc[i][1], acc[i][2], acc[i][3]);
        *(float4*)&g_k3v_part[((size_t)(s * 64 + bh) * 128 + rt * 8 + i) * 64 + ct * 4] = t;
    }
}

__global__ void k3v_reduce_kernel()
{
    int idx = blockIdx.x * blockDim.x + threadIdx.x;  // 524288
    float s = 0.f;
    #pragma unroll
    for (int p = 0; p < 8; p++) s += g_k3v_part[(size_t)p * 524288 + idx];
    g_k3v[idx] = s;
}

// =====================================================================
// y2 = inv(g_Va) @ k3v  per head. block per head. dyn smem 98304 B
// =====================================================================
__global__ __launch_bounds__(256) void y2_kernel()
{
    extern __shared__ float sm[];
    float* At = sm;           // [k=128][r=128]  (inv transposed)
    float* Bs = sm + 16384;   // [k=128][d=64]
    int bh = blockIdx.x, tid = threadIdx.x;
    const float* inv = g_Va + bh * 16384;
    const float* kv  = g_k3v + bh * 8192;

    #pragma unroll
    for (int i = 0; i < 16; i++) {
        int f = i * 1024 + tid * 4; int r = f >> 7, k0 = f & 127;
        float4 t = *(const float4*)&inv[f];
        At[(k0 + 0) * 128 + r] = t.x; At[(k0 + 1) * 128 + r] = t.y;
        At[(k0 + 2) * 128 + r] = t.z; At[(k0 + 3) * 128 + r] = t.w;
    }
    #pragma unroll
    for (int i = 0; i < 8; i++) {
        int f = i * 1024 + tid * 4;
        *(float4*)&Bs[f] = *(const float4*)&kv[f];
    }
    __syncthreads();

    int rt = tid >> 4, ct = tid & 15;
    float acc[8][4] = {};
    for (int k = 0; k < 128; k++) {
        float4 a0 = *(const float4*)&At[k * 128 + rt * 8];
        float4 a1 = *(const float4*)&At[k * 128 + rt * 8 + 4];
        float4 b  = *(const float4*)&Bs[k * 64 + ct * 4];
        float av[8] = {a0.x, a0.y, a0.z, a0.w, a1.x, a1.y, a1.z, a1.w};
        #pragma unroll
        for (int i = 0; i < 8; i++) {
            acc[i][0] += av[i] * b.x; acc[i][1] += av[i] * b.y;
            acc[i][2] += av[i] * b.z; acc[i][3] += av[i] * b.w;
        }
    }
    #pragma unroll
    for (int i = 0; i < 8; i++) {
        float4 t = make_float4(acc[i][0], acc[i][1], acc[i][2], acc[i][3]);
        *(float4*)&g_y2[(size_t)bh * 8192 + (rt * 8 + i) * 64 + ct * 4] = t;
    }
}

// =====================================================================
// X1 = kernel_1 @ y2 per head, written straight into [b,l,h*64+d] layout.
// grid (32, 64). dyn smem 98304 B
// =====================================================================
__global__ __launch_bounds__(256) void x1_kernel()
{
    extern __shared__ float sm[];
    float* At = sm;           // [m=128][l=128]
    float* Bs = sm + 16384;   // [m=128][d=64]
    int bh = blockIdx.y, l0 = blockIdx.x * 128, tid = threadIdx.x;

    #pragma unroll
    for (int i = 0; i < 16; i++) {
        int f = i * 1024 + tid * 4; int r = f >> 7, m0 = f & 127;
        float4 t = *(const float4*)&g_k1[(size_t)bh * (L_ * M_) + (size_t)(l0 + r) * 128 + m0];
        At[(m0 + 0) * 128 + r] = t.x; At[(m0 + 1) * 128 + r] = t.y;
        At[(m0 + 2) * 128 + r] = t.z; At[(m0 + 3) * 128 + r] = t.w;
    }
    #pragma unroll
    for (int i = 0; i < 8; i++) {
        int f = i * 1024 + tid * 4;
        *(float4*)&Bs[f] = *(const float4*)&g_y2[(size_t)bh * 8192 + f];
    }
    __syncthreads();

    int rt = tid >> 4, ct = tid & 15;
    float acc[8][4] = {};
    for (int k = 0; k < 128; k++) {
        float4 a0 = *(const float4*)&At[k * 128 + rt * 8];
        float4 a1 = *(const float4*)&At[k * 128 + rt * 8 + 4];
        float4 b  = *(const float4*)&Bs[k * 64 + ct * 4];
        float av[8] = {a0.x, a0.y, a0.z, a0.w, a1.x, a1.y, a1.z, a1.w};
        #pragma unroll
        for (int i = 0; i < 8; i++) {
            acc[i][0] += av[i] * b.x; acc[i][1] += av[i] * b.y;
            acc[i][2] += av[i] * b.z; acc[i][3] += av[i] * b.w;
        }
    }
    int b = bh >> 4, h = bh & 15;
    #pragma unroll
    for (int i = 0; i < 8; i++) {
        int l = l0 + rt * 8 + i;
        float4 t = make_float4(acc[i][0], acc[i][1], acc[i][2], acc[i][3]);
        *(float4*)&g_x[((size_t)(b * L_ + l)) * DM_ + h * 64 + ct * 4] = t;
    }
}

// =====================================================================
// launch
// =====================================================================
extern "C" void kernel_launch(void* const* d_in, const int* in_sizes, int n_in,
                              void* d_out, int out_size)
{
    const float* queries = (const float*)d_in[0];
    const float* keys    = (const float*)d_in[1];
    const float* values  = (const float*)d_in[2];
    const float* Wq = (const float*)d_in[3];
    const float* bq = (const float*)d_in[4];
    const float* Wk = (const float*)d_in[5];
    const float* bk = (const float*)d_in[6];
    const float* Wv = (const float*)d_in[7];
    const float* bv = (const float*)d_in[8];
    const float* Wo = (const float*)d_in[9];
    const float* bo = (const float*)d_in[10];
    float* out = (float*)d_out;

    cudaFuncSetAttribute(k1_kernel,      cudaFuncAttributeMaxDynamicSharedMemorySize, 57344);
    cudaFuncSetAttribute(k3score_kernel, cudaFuncAttributeMaxDynamicSharedMemorySize, 65536);
    cudaFuncSetAttribute(k2_kernel,      cudaFuncAttributeMaxDynamicSharedMemorySize, 131072);
    cudaFuncSetAttribute(bmm_kernel,     cudaFuncAttributeMaxDynamicSharedMemorySize, 81920);
    cudaFuncSetAttribute(y2_kernel,      cudaFuncAttributeMaxDynamicSharedMemorySize, 98304);
    cudaFuncSetAttribute(x1_kernel,      cudaFuncAttributeMaxDynamicSharedMemorySize, 98304);

    dim3 gemm_grid(8, 128);   // N tiles x M tiles

    // projections -> g_q / g_k / g_v (bhld layout)
    sgemm_kernel<<<gemm_grid, 256>>>(queries, Wq, bq, nullptr, 0);
    sgemm_kernel<<<gemm_grid, 256>>>(keys,    Wk, bk, nullptr, 1);
    sgemm_kernel<<<gemm_grid, 256>>>(values,  Wv, bv, nullptr, 2);

    // landmark pooling
    pool_kernel<<<2048, 256>>>();

    // kernel_1 (fused score+softmax over 128)
    k1_kernel<<<dim3(128, 64), 256, 57344>>>();

    // kernel_3 scores + softmax over 4096
    k3score_kernel<<<dim3(32, 64), 256, 65536>>>();
    softmax4096_kernel<<<8192, 256>>>();

    // kernel_2 + Newton-Schulz pseudo-inverse
    k2_kernel<<<64, 256, 131072>>>();
    vinit_kernel<<<64, 256>>>();
    int cur = 4, nxt = 5;   // g_Va / g_Vb
    for (int it = 0; it < 6; it++) {
        bmm_kernel<<<dim3(4, 64), 256, 81920>>>(0,   cur, 0,   1,   1.0f,  0.0f);  // P  = K@V
        bmm_kernel<<<dim3(4, 64), 256, 81920>>>(1,   1,   1,   2,  -1.0f,  7.0f);  // M1 = 7P - P@P
        bmm_kernel<<<dim3(4, 64), 256, 81920>>>(1,   2,   1,   3,  -1.0f, 15.0f);  // M2 = 15P - P@M1
        bmm_kernel<<<dim3(4, 64), 256, 81920>>>(cur, 3,   cur, nxt, -0.25f, 3.25f);// V' = .25(13V - V@M2)
        int t = cur; cur = nxt; nxt = t;
    }
    // after 6 iterations cur == 4 (g_Va) holds the pseudo-inverse

    // kernel_3 @ v  (split-K 8 + reduce)
    k3v_kernel<<<dim3(8, 64), 256, 24576>>>();
    k3v_reduce_kernel<<<2048, 256>>>();

    // y2 = inv @ k3v ; X1 = kernel_1 @ y2 -> g_x (b,l,h*64+d)
    y2_kernel<<<64, 256, 98304>>>();
    x1_kernel<<<dim3(32, 64), 256, 98304>>>();

    // output projection
    sgemm_kernel<<<gemm_grid, 256>>>(queries /*unused*/, Wo, bo, out, 3);
}

// round 3
// speedup vs baseline: 1.6999x; 1.6999x over previous
#include <cuda_runtime.h>
#include <cuda_bf16.h>
#include <cstdint>

// ---------------- problem constants ----------------
#define B_    4
#define L_    4096
#define DM_   1024
#define H_    16
#define D_    64
#define M_    128
#define BH_   64          // B*H
#define SEG_  32          // L/M
#define NTOK_ 16384       // B*L

// ---------------- scratch (device globals; no allocations allowed) ----------------
__device__ float g_q [BH_ * L_ * D_];          // [bh][l][d]
__device__ float g_k [BH_ * L_ * D_];
__device__ float g_v [BH_ * L_ * D_];
__device__ float g_Ql[BH_ * M_ * D_];          // [bh][m][d]
__device__ float g_Kl[BH_ * M_ * D_];
__device__ float g_k1[(size_t)BH_ * L_ * M_];  // [bh][l][m]   softmaxed
__device__ float g_k3[(size_t)BH_ * M_ * L_];  // [bh][m][l]   raw then softmaxed in place
__device__ float g_k2[BH_ * M_ * M_];          // [bh][n][m]   softmaxed
__device__ float g_P [BH_ * M_ * M_];
__device__ float g_M1[BH_ * M_ * M_];
__device__ float g_M2[BH_ * M_ * M_];
__device__ float g_Va[BH_ * M_ * M_];
__device__ float g_Vb[BH_ * M_ * M_];
__device__ float g_k3v_part[8 * BH_ * M_ * D_];
__device__ float g_k3v[BH_ * M_ * D_];         // [bh][m][d]
__device__ float g_y2 [BH_ * M_ * D_];         // [bh][m][d]

// bf16 split buffers for the tensor-core GEMMs
__device__ __align__(16) __nv_bfloat16 g_ah[(size_t)NTOK_ * DM_];   // A hi  [row][k]
__device__ __align__(16) __nv_bfloat16 g_al[(size_t)NTOK_ * DM_];   // A lo
__device__ __align__(16) __nv_bfloat16 g_wh[DM_ * DM_];             // W^T hi [n][k]
__device__ __align__(16) __nv_bfloat16 g_wl[DM_ * DM_];             // W^T lo

// =====================================================================
// baseline-PTX helpers (mma.sync / ldmatrix / cp.async — no tcgen05!)
// =====================================================================
__device__ __forceinline__ uint32_t smem_to_u32(const void* p) {
    uint32_t a;
    asm("{ .reg .u64 t; cvta.to.shared.u64 t, %1; cvt.u32.u64 %0, t; }" : "=r"(a) : "l"(p));
    return a;
}
__device__ __forceinline__ void ldsm4(uint32_t* r, uint32_t addr) {
    asm volatile("ldmatrix.sync.aligned.m8n8.x4.shared.b16 {%0,%1,%2,%3}, [%4];"
        : "=r"(r[0]), "=r"(r[1]), "=r"(r[2]), "=r"(r[3]) : "r"(addr));
}
__device__ __forceinline__ void mma16816(float* d, const uint32_t* a, const uint32_t* b) {
    asm volatile("mma.sync.aligned.m16n8k16.row.col.f32.bf16.bf16.f32 "
        "{%0,%1,%2,%3}, {%4,%5,%6,%7}, {%8,%9}, {%0,%1,%2,%3};"
        : "+f"(d[0]), "+f"(d[1]), "+f"(d[2]), "+f"(d[3])
        : "r"(a[0]), "r"(a[1]), "r"(a[2]), "r"(a[3]), "r"(b[0]), "r"(b[1]));
}
#define CP_ASYNC16(dst, src) \
    asm volatile("cp.async.cg.shared.global [%0], [%1], 16;" :: "r"(dst), "l"(src))
#define CP_COMMIT()  asm volatile("cp.async.commit_group;" ::: "memory")
#define CP_WAIT(n)   asm volatile("cp.async.wait_group %0;" :: "n"(n) : "memory")

// =====================================================================
// conversion kernels (fp32 -> bf16 hi/lo split)
// =====================================================================
__global__ void conv_act_kernel(const float* __restrict__ src)
{
    size_t i4 = (size_t)blockIdx.x * 256 + threadIdx.x;       // float4 index
    float4 v = *(const float4*)&src[i4 * 4];
    __nv_bfloat16 h[4], l[4];
    float a[4] = {v.x, v.y, v.z, v.w};
    #pragma unroll
    for (int i = 0; i < 4; i++) {
        h[i] = __float2bfloat16(a[i]);
        l[i] = __float2bfloat16(a[i] - __bfloat162float(h[i]));
    }
    *(uint2*)&g_ah[i4 * 4] = *(uint2*)h;
    *(uint2*)&g_al[i4 * 4] = *(uint2*)l;
}

// W [k][n] -> Wt hi/lo [n][k]
__global__ void conv_wt_kernel(const float* __restrict__ W)
{
    __shared__ float t[32][33];
    int x = blockIdx.x * 32 + threadIdx.x;   // n
    int y = blockIdx.y * 32 + threadIdx.y;   // k
    #pragma unroll
    for (int j = 0; j < 32; j += 8) t[threadIdx.y + j][threadIdx.x] = W[(size_t)(y + j) * 1024 + x];
    __syncthreads();
    int xo = blockIdx.y * 32 + threadIdx.x;  // k (output col)
    int yo = blockIdx.x * 32 + threadIdx.y;  // n (output row)
    #pragma unroll
    for (int j = 0; j < 32; j += 8) {
        float v = t[threadIdx.x][threadIdx.y + j];
        __nv_bfloat16 h = __float2bfloat16(v);
        g_wh[(size_t)(yo + j) * 1024 + xo] = h;
        g_wl[(size_t)(yo + j) * 1024 + xo] = __float2bfloat16(v - __bfloat162float(h));
    }
}

// =====================================================================
// mma.sync bf16-split GEMM:
//   C[16384,1024] = (Ah+Al) @ (Wh+Wl)^T + bias   (3-product split, fp32 accum)
// CTA tile 128x128, BK=32, double-buffered cp.async, 8 warps (2M x 4N),
// warp tile 64x32 via m16n8k16.
// mode 0/1/2: scatter into g_q/g_k/g_v [bh][l][d]; mode 3: row-major outp.
// dyn smem = 81920 B
// =====================================================================
#define PITCH   40                      // bf16 per smem row (80 B)
#define TSZ     (128 * PITCH * 2)       // 10240 B per tile array
#define BUFSZ   (4 * TSZ)               // 40960 B per stage
#define OFF_AH  0
#define OFF_AL  (1 * TSZ)
#define OFF_BH  (2 * TSZ)
#define OFF_BL  (3 * TSZ)

__global__ __launch_bounds__(256) void gemm_mma_kernel(
    const __nv_bfloat16* __restrict__ Ah, const __nv_bfloat16* __restrict__ Al,
    const float* __restrict__ bias, float* __restrict__ outp, int mode)
{
    extern __shared__ char smem[];
    const uint32_t sbase = smem_to_u32(smem);

    const int tid  = threadIdx.x;
    const int lane = tid & 31;
    const int w    = tid >> 5;
    const int wm   = w >> 2;     // 0..1  (64-row subtile)
    const int wn   = w & 3;      // 0..3  (32-col subtile)
    const int n0 = blockIdx.x * 128;
    const int m0 = blockIdx.y * 128;

    float acc[4][4][4];
    #pragma unroll
    for (int i = 0; i < 4; i++)
        #pragma unroll
        for (int j = 0; j < 4; j++)
            #pragma unroll
            for (int t = 0; t < 4; t++) acc[i][j][t] = 0.f;

    // ---- chunk loader (cp.async): 2048 x 16B per chunk ----
    auto load_chunk = [&](int c, int buf) {
        const int k0 = c * 32;
        const uint32_t sb = sbase + buf * BUFSZ;
        #pragma unroll
        for (int i = 0; i < 8; i++) {
            int q = tid + i * 256;            // 0..2047
            int arr = q >> 9;                 // 0..3
            int r   = (q >> 2) & 127;
            int c4  = q & 3;
            uint32_t dst = sb + arr * TSZ + r * 80 + c4 * 16;
            const __nv_bfloat16* src;
            if      (arr == 0) src = &Ah  [(size_t)(m0 + r) * 1024 + k0 + c4 * 8];
            else if (arr == 1) src = &Al  [(size_t)(m0 + r) * 1024 + k0 + c4 * 8];
            else if (arr == 2) src = &g_wh[(size_t)(n0 + r) * 1024 + k0 + c4 * 8];
            else               src = &g_wl[(size_t)(n0 + r) * 1024 + k0 + c4 * 8];
            CP_ASYNC16(dst, src);
        }
        CP_COMMIT();
    };

    // ---- compute one 32-wide K chunk from stage buf ----
    auto compute_chunk = [&](int buf) {
        const uint32_t S = sbase + buf * BUFSZ;
        #pragma unroll
        for (int k16 = 0; k16 < 2; k16++) {
            const uint32_t kb = (uint32_t)(k16 * 32);   // byte offset of k16 within row
            // A fragments: [term][mt][4]
            uint32_t af[2][4][4];
            #pragma unroll
            for (int term = 0; term < 2; term++) {
                uint32_t base = S + (term ? OFF_AL : OFF_AH);
                #pragma unroll
                for (int mt = 0; mt < 4; mt++) {
                    uint32_t addr = base
                        + (uint32_t)((wm * 64 + mt * 16 + (lane & 15)) * 80)
                        + kb + (uint32_t)((lane >> 4) * 16);
                    ldsm4(af[term][mt], addr);
                }
            }
            // B fragments: [term][npair][4]  (npair covers two n8 tiles)
            uint32_t bf[2][2][4];
            #pragma unroll
            for (int term = 0; term < 2; term++) {
                uint32_t base = S + (term ? OFF_BL : OFF_BH);
                #pragma unroll
                for (int np = 0; np < 2; np++) {
                    uint32_t nrow = (uint32_t)(wn * 32 + np * 16 + ((lane >> 4) * 8) + (lane & 7));
                    uint32_t addr = base + nrow * 80 + kb + (uint32_t)(((lane >> 3) & 1) * 16);
                    ldsm4(bf[term][np], addr);
                }
            }
            // 3-product MMAs
            #pragma unroll
            for (int mt = 0; mt < 4; mt++) {
                #pragma unroll
                for (int nt = 0; nt < 4; nt++) {
                    float* d = acc[mt][nt];
                    const uint32_t* bh_ = &bf[0][nt >> 1][(nt & 1) * 2];
                    const uint32_t* bl_ = &bf[1][nt >> 1][(nt & 1) * 2];
                    mma16816(d, af[0][mt], bh_);
                    mma16816(d, af[0][mt], bl_);
                    mma16816(d, af[1][mt], bh_);
                }
            }
        }
    };

    // ---- pipeline: 32 chunks, 2-deep ----
    load_chunk(0, 0);
    #pragma unroll 1
    for (int c = 0; c < 32; c++) {
        if (c + 1 < 32) {
            load_chunk(c + 1, (c + 1) & 1);
            CP_WAIT(1);
        } else {
            CP_WAIT(0);
        }
        __syncthreads();
        compute_chunk(c & 1);
        __syncthreads();
    }

    // ---- epilogue ----
    #pragma unroll
    for (int mt = 0; mt < 4; mt++) {
        #pragma unroll
        for (int nt = 0; nt < 4; nt++) {
            int c = n0 + wn * 32 + nt * 8 + (lane & 3) * 2;
            float b0 = bias[c], b1 = bias[c + 1];
            #pragma unroll
            for (int half = 0; half < 2; half++) {
                int r = m0 + wm * 64 + mt * 16 + (lane >> 2) + half * 8;
                float2 t;
                t.x = acc[mt][nt][half * 2 + 0] + b0;
                t.y = acc[mt][nt][half * 2 + 1] + b1;
                if (mode == 3) {
                    *(float2*)&outp[(size_t)r * 1024 + c] = t;
                } else {
                    float* dst = (mode == 0) ? g_q : ((mode == 1) ? g_k : g_v);
                    int b = r >> 12, l = r & 4095;
                    int h = c >> 6, d = c & 63;
                    *(float2*)&dst[(((size_t)(b * 16 + h) * 4096) + l) * 64 + d] = t;
                }
            }
        }
    }
}

// =====================================================================
// landmark pooling: mean over 32-token segments of q and k
// =====================================================================
__global__ void pool_kernel()
{
    int idx = blockIdx.x * blockDim.x + threadIdx.x;   // BH*M*D = 524288
    int d  = idx & 63;
    int m  = (idx >> 6) & 127;
    int bh = idx >> 13;
    size_t base = ((size_t)bh * L_ + m * SEG_) * D_ + d;
    float sq = 0.f, sk = 0.f;
    #pragma unroll
    for (int s = 0; s < SEG_; s++) { sq += g_q[base + s * D_]; sk += g_k[base + s * D_]; }
    g_Ql[idx] = sq * (1.f / SEG_);
    g_Kl[idx] = sk * (1.f / SEG_);
}

// =====================================================================
// kernel_1 = softmax(q @ K_l^T) fused (rows of 128) -> g_k1
// =====================================================================
__global__ __launch_bounds__(256) void k1_kernel()
{
    extern __shared__ float sm[];
    float* Klt = sm;                 // [d=64][m=128]
    float* Qt  = sm + 8192;          // [d=64][r=32]
    float* S   = sm + 8192 + 2048;   // [r=32][m=128]
    int bh = blockIdx.y, l0 = blockIdx.x * 32, tid = threadIdx.x;

    const float* Kl = g_Kl + bh * 8192;
    #pragma unroll
    for (int i = 0; i < 8; i++) {
        int f = i * 1024 + tid * 4; int m = f >> 6, d0 = f & 63;
        float4 t = *(const float4*)&Kl[f];
        Klt[(d0 + 0) * 128 + m] = t.x; Klt[(d0 + 1) * 128 + m] = t.y;
        Klt[(d0 + 2) * 128 + m] = t.z; Klt[(d0 + 3) * 128 + m] = t.w;
    }
    const float* qp = g_q + ((size_t)bh * L_ + l0) * D_;
    #pragma unroll
    for (int i = 0; i < 2; i++) {
        int f = i * 1024 + tid * 4; int r = f >> 6, d0 = f & 63;
        float4 t = *(const float4*)&qp[f];
        Qt[(d0 + 0) * 32 + r] = t.x; Qt[(d0 + 1) * 32 + r] = t.y;
        Qt[(d0 + 2) * 32 + r] = t.z; Qt[(d0 + 3) * 32 + r] = t.w;
    }
    __syncthreads();

    int rb = (tid >> 5) * 4, cb = (tid & 31) * 4;
    float acc[4][4] = {};
    for (int d = 0; d < 64; d++) {
        float a0 = Qt[d * 32 + rb + 0], a1 = Qt[d * 32 + rb + 1];
        float a2 = Qt[d * 32 + rb + 2], a3 = Qt[d * 32 + rb + 3];
        float4 b = *(const float4*)&Klt[d * 128 + cb];
        acc[0][0] += a0 * b.x; acc[0][1] += a0 * b.y; acc[0][2] += a0 * b.z; acc[0][3] += a0 * b.w;
        acc[1][0] += a1 * b.x; acc[1][1] += a1 * b.y; acc[1][2] += a1 * b.z; acc[1][3] += a1 * b.w;
        acc[2][0] += a2 * b.x; acc[2][1] += a2 * b.y; acc[2][2] += a2 * b.z; acc[2][3] += a2 * b.w;
        acc[3][0] += a3 * b.x; acc[3][1] += a3 * b.y; acc[3][2] += a3 * b.z; acc[3][3] += a3 * b.w;
    }
    #pragma unroll
    for (int i = 0; i < 4; i++)
        #pragma unroll
        for (int j = 0; j < 4; j++) S[(rb + i) * 128 + cb + j] = acc[i][j];
    __syncthreads();

    int lane = tid & 31, w = tid >> 5;
    for (int rr = 0; rr < 4; rr++) {
        int row = w * 4 + rr;
        float x0 = S[row * 128 + lane],      x1 = S[row * 128 + lane + 32];
        float x2 = S[row * 128 + lane + 64], x3 = S[row * 128 + lane + 96];
        float mx = fmaxf(fmaxf(x0, x1), fmaxf(x2, x3));
        #pragma unroll
        for (int o = 16; o; o >>= 1) mx = fmaxf(mx, __shfl_xor_sync(0xffffffffu, mx, o));
        float e0 = __expf(x0 - mx), e1 = __expf(x1 - mx);
        float e2 = __expf(x2 - mx), e3 = __expf(x3 - mx);
        float s = e0 + e1 + e2 + e3;
        #pragma unroll
        for (int o = 16; o; o >>= 1) s += __shfl_xor_sync(0xffffffffu, s, o);
        float inv = 1.f / s;
        float* o = g_k1 + (size_t)bh * (M_ * L_) + (size_t)(l0 + row) * 128;
        o[lane] = e0 * inv; o[lane + 32] = e1 * inv; o[lane + 64] = e2 * inv; o[lane + 96] = e3 * inv;
    }
}

// =====================================================================
// kernel_3 raw scores: S[m][l] = Q_l[m] . k[l]  -> g_k3 (raw)
// =====================================================================
__global__ __launch_bounds__(256) void k3score_kernel()
{
    extern __shared__ float sm[];
    float* Qlt = sm;          // [d][m]
    float* Kt  = sm + 8192;   // [d][l]
    int bh = blockIdx.y, l0 = blockIdx.x * 128, tid = threadIdx.x;

    const float* Ql = g_Ql + bh * 8192;
    #pragma unroll
    for (int i = 0; i < 8; i++) {
        int f = i * 1024 + tid * 4; int m = f >> 6, d0 = f & 63;
        float4 t = *(const float4*)&Ql[f];
        Qlt[(d0 + 0) * 128 + m] = t.x; Qlt[(d0 + 1) * 128 + m] = t.y;
        Qlt[(d0 + 2) * 128 + m] = t.z; Qlt[(d0 + 3) * 128 + m] = t.w;
    }
    const float* kp = g_k + ((size_t)bh * L_ + l0) * D_;
    #pragma unroll
    for (int i = 0; i < 8; i++) {
        int f = i * 1024 + tid * 4; int r = f >> 6, d0 = f & 63;
        float4 t = *(const float4*)&kp[f];
        Kt[(d0 + 0) * 128 + r] = t.x; Kt[(d0 + 1) * 128 + r] = t.y;
        Kt[(d0 + 2) * 128 + r] = t.z; Kt[(d0 + 3) * 128 + r] = t.w;
    }
    __syncthreads();

    int tm = tid >> 4, tn = tid & 15;
    float acc[8][8] = {};
    for (int d = 0; d < 64; d++) {
        float4 a0 = *(const float4*)&Qlt[d * 128 + tm * 8];
        float4 a1 = *(const float4*)&Qlt[d * 128 + tm * 8 + 4];
        float4 b0 = *(const float4*)&Kt[d * 128 + tn * 8];
        float4 b1 = *(const float4*)&Kt[d * 128 + tn * 8 + 4];
        float av[8] = {a0.x, a0.y, a0.z, a0.w, a1.x, a1.y, a1.z, a1.w};
        float bv[8] = {b0.x, b0.y, b0.z, b0.w, b1.x, b1.y, b1.z, b1.w};
        #pragma unroll
        for (int i = 0; i < 8; i++)
            #pragma unroll
            for (int j = 0; j < 8; j++) acc[i][j] += av[i] * bv[j];
    }
    float* o = g_k3 + (size_t)bh * (M_ * L_);
    #pragma unroll
    for (int i = 0; i < 8; i++) {
        size_t base = (size_t)(tm * 8 + i) * L_ + l0 + tn * 8;
        float4 v0 = make_float4(acc[i][0], acc[i][1], acc[i][2], acc[i][3]);
        float4 v1 = make_float4(acc[i][4], acc[i][5], acc[i][6], acc[i][7]);
        *(float4*)&o[base] = v0; *(float4*)&o[base + 4] = v1;
    }
}

// =====================================================================
// row softmax over 4096 (in place on g_k3)
// =====================================================================
__global__ __launch_bounds__(256) void softmax4096_kernel()
{
    size_t row = blockIdx.x;
    float* p = g_k3 + row * 4096;
    int tid = threadIdx.x;
    float v[16];
    float mx = -1e30f;
    #pragma unroll
    for (int i = 0; i < 4; i++) {
        float4 t = *(const float4*)&p[i * 1024 + tid * 4];
        v[i * 4 + 0] = t.x; v[i * 4 + 1] = t.y; v[i * 4 + 2] = t.z; v[i * 4 + 3] = t.w;
        mx = fmaxf(mx, fmaxf(fmaxf(t.x, t.y), fmaxf(t.z, t.w)));
    }
    __shared__ float smx[8], ssm[8], sres;
    #pragma unroll
    for (int o = 16; o; o >>= 1) mx = fmaxf(mx, __shfl_xor_sync(0xffffffffu, mx, o));
    if ((tid & 31) == 0) smx[tid >> 5] = mx;
    __syncthreads();
    if (tid == 0) {
        float m = smx[0];
        #pragma unroll
        for (int i = 1; i < 8; i++) m = fmaxf(m, smx[i]);
        sres = m;
    }
    __syncthreads();
    float MX = sres;
    float s = 0.f;
    #pragma unroll
    for (int i = 0; i < 16; i++) { v[i] = __expf(v[i] - MX); s += v[i]; }
    #pragma unroll
    for (int o = 16; o; o >>= 1) s += __shfl_xor_sync(0xffffffffu, s, o);
    if ((tid & 31) == 0) ssm[tid >> 5] = s;
    __syncthreads();
    if (tid == 0) {
        float t = 0.f;
        #pragma unroll
        for (int i = 0; i < 8; i++) t += ssm[i];
        sres = 1.f / t;
    }
    __syncthreads();
    float inv = sres;
    #pragma unroll
    for (int i = 0; i < 4; i++) {
        float4 t = make_float4(v[i*4]*inv, v[i*4+1]*inv, v[i*4+2]*inv, v[i*4+3]*inv);
        *(float4*)&p[i * 1024 + tid * 4] = t;
    }
}

// =====================================================================
// kernel_2 = softmax(Q_l @ K_l^T) fused. block per head.
// =====================================================================
__global__ __launch_bounds__(256) void k2_kernel()
{
    extern __shared__ float sm[];
    float* Qlt = sm;            // [d][n]
    float* Klt = sm + 8192;     // [d][m]
    float* S   = sm + 16384;    // [n][m]
    int bh = blockIdx.x, tid = threadIdx.x;

    const float* Ql = g_Ql + bh * 8192;
    const float* Kl = g_Kl + bh * 8192;
    #pragma unroll
    for (int i = 0; i < 8; i++) {
        int f = i * 1024 + tid * 4; int m = f >> 6, d0 = f & 63;
        float4 tq = *(const float4*)&Ql[f];
        float4 tk = *(const float4*)&Kl[f];
        Qlt[(d0 + 0) * 128 + m] = tq.x; Qlt[(d0 + 1) * 128 + m] = tq.y;
        Qlt[(d0 + 2) * 128 + m] = tq.z; Qlt[(d0 + 3) * 128 + m] = tq.w;
        Klt[(d0 + 0) * 128 + m] = tk.x; Klt[(d0 + 1) * 128 + m] = tk.y;
        Klt[(d0 + 2) * 128 + m] = tk.z; Klt[(d0 + 3) * 128 + m] = tk.w;
    }
    __syncthreads();

    int tm = tid >> 4, tn = tid & 15;
    float acc[8][8] = {};
    for (int d = 0; d < 64; d++) {
        float4 a0 = *(const float4*)&Qlt[d * 128 + tm * 8];
        float4 a1 = *(const float4*)&Qlt[d * 128 + tm * 8 + 4];
        float4 b0 = *(const float4*)&Klt[d * 128 + tn * 8];
        float4 b1 = *(const float4*)&Klt[d * 128 + tn * 8 + 4];
        float av[8] = {a0.x, a0.y, a0.z, a0.w, a1.x, a1.y, a1.z, a1.w};
        float bv[8] = {b0.x, b0.y, b0.z, b0.w, b1.x, b1.y, b1.z, b1.w};
        #pragma unroll
        for (int i = 0; i < 8; i++)
            #pragma unroll
            for (int j = 0; j < 8; j++) acc[i][j] += av[i] * bv[j];
    }
    #pragma unroll
    for (int i = 0; i < 8; i++)
        #pragma unroll
        for (int j = 0; j < 8; j++) S[(tm * 8 + i) * 128 + tn * 8 + j] = acc[i][j];
    __syncthreads();

    int lane = tid & 31, w = tid >> 5;
    for (int rr = 0; rr < 16; rr++) {
        int row = w * 16 + rr;
        float x0 = S[row * 128 + lane],      x1 = S[row * 128 + lane + 32];
        float x2 = S[row * 128 + lane + 64], x3 = S[row * 128 + lane + 96];
        float mx = fmaxf(fmaxf(x0, x1), fmaxf(x2, x3));
        #pragma unroll
        for (int o = 16; o; o >>= 1) mx = fmaxf(mx, __shfl_xor_sync(0xffffffffu, mx, o));
        float e0 = __expf(x0 - mx), e1 = __expf(x1 - mx);
        float e2 = __expf(x2 - mx), e3 = __expf(x3 - mx);
        float s = e0 + e1 + e2 + e3;
        #pragma unroll
        for (int o = 16; o; o >>= 1) s += __shfl_xor_sync(0xffffffffu, s, o);
        float inv = 1.f / s;
        float* o = g_k2 + bh * 16384 + row * 128;
        o[lane] = e0 * inv; o[lane + 32] = e1 * inv; o[lane + 64] = e2 * inv; o[lane + 96] = e3 * inv;
    }
}

// =====================================================================
// V0 = K^T / max(colsum(K))
// =====================================================================
__global__ __launch_bounds__(256) void vinit_kernel()
{
    int bh = blockIdx.x, tid = threadIdx.x;
    const float* K = g_k2 + bh * 16384;
    __shared__ float cs[128];
    __shared__ float sscale;
    if (tid < 128) {
        float s = 0.f;
        for (int r = 0; r < 128; r++) s += K[r * 128 + tid];
        cs[tid] = s;
    }
    __syncthreads();
    if (tid == 0) {
        float m = cs[0];
        for (int i = 1; i < 128; i++) m = fmaxf(m, cs[i]);
        sscale = 1.f / m;
    }
    __syncthreads();
    float scale = sscale;
    for (int f = tid; f < 16384; f += 256) {
        int i = f >> 7, j = f & 127;
        g_Va[bh * 16384 + f] = scale * K[j * 128 + i];
    }
}

// =====================================================================
// batched 128x128 bmm for Newton-Schulz: OUT = alpha*(A@B) + beta*C
// =====================================================================
__device__ __forceinline__ float* bufsel(int s)
{
    switch (s) {
        case 0: return g_k2; case 1: return g_P; case 2: return g_M1;
        case 3: return g_M2; case 4: return g_Va; default: return g_Vb;
    }
}

__global__ __launch_bounds__(256) void bmm_kernel(int as, int bs, int cs2, int os,
                                                  float alpha, float beta)
{
    extern __shared__ float sm[];
    float* Bs = sm;            // [k=128][c=128]
    float* At = sm + 16384;    // [k=128][r=32]
    int bh = blockIdx.y, r0 = blockIdx.x * 32, tid = threadIdx.x;
    const float* A  = bufsel(as)  + bh * 16384;
    const float* Bm = bufsel(bs)  + bh * 16384;
    const float* C  = bufsel(cs2) + bh * 16384;
    float* O        = bufsel(os)  + bh * 16384;

    #pragma unroll
    for (int i = 0; i < 16; i++) {
        int f = i * 1024 + tid * 4;
        *(float4*)&Bs[f] = *(const float4*)&Bm[f];
    }
    #pragma unroll
    for (int i = 0; i < 4; i++) {
        int f = i * 1024 + tid * 4; int r = f >> 7, k0 = f & 127;
        float4 t = *(const float4*)&A[(r0 + r) * 128 + k0];
        At[(k0 + 0) * 32 + r] = t.x; At[(k0 + 1) * 32 + r] = t.y;
        At[(k0 + 2) * 32 + r] = t.z; At[(k0 + 3) * 32 + r] = t.w;
    }
    __syncthreads();

    int rb = (tid >> 5) * 4, cb = (tid & 31) * 4;
    float acc[4][4] = {};
    for (int k = 0; k < 128; k++) {
        float a0 = At[k * 32 + rb + 0], a1 = At[k * 32 + rb + 1];
        float a2 = At[k * 32 + rb + 2], a3 = At[k * 32 + rb + 3];
        float4 b = *(const float4*)&Bs[k * 128 + cb];
        acc[0][0] += a0 * b.x; acc[0][1] += a0 * b.y; acc[0][2] += a0 * b.z; acc[0][3] += a0 * b.w;
        acc[1][0] += a1 * b.x; acc[1][1] += a1 * b.y; acc[1][2] += a1 * b.z; acc[1][3] += a1 * b.w;
        acc[2][0] += a2 * b.x; acc[2][1] += a2 * b.y; acc[2][2] += a2 * b.z; acc[2][3] += a2 * b.w;
        acc[3][0] += a3 * b.x; acc[3][1] += a3 * b.y; acc[3][2] += a3 * b.z; acc[3][3] += a3 * b.w;
    }
    #pragma unroll
    for (int i = 0; i < 4; i++)
        #pragma unroll
        for (int j = 0; j < 4; j++) {
            int idx = (r0 + rb + i) * 128 + cb + j;
            O[idx] = alpha * acc[i][j] + beta * C[idx];
        }
}

// =====================================================================
// k3v partial: (kernel_3 @ v) split-K(8)
// =====================================================================
__global__ __launch_bounds__(256) void k3v_kernel()
{
    extern __shared__ float sm[];
    float* At = sm;           // [k=32][m=128]
    float* Vs = sm + 4096;    // [k=32][d=64]
    int s = blockIdx.x, bh = blockIdx.y, tid = threadIdx.x;
    int kbase = s * 512;
    int rt = tid >> 4, ct = tid & 15;
    float acc[8][4] = {};

    for (int kt = 0; kt < 512; kt += 32) {
        __syncthreads();
        #pragma unroll
        for (int i = 0; i < 4; i++) {
            int f = i * 1024 + tid * 4; int m = f >> 5, kk = f & 31;
            float4 t = *(const float4*)&g_k3[(size_t)bh * (M_ * L_) + (size_t)m * L_ + kbase + kt + kk];
            At[(kk + 0) * 128 + m] = t.x; At[(kk + 1) * 128 + m] = t.y;
            At[(kk + 2) * 128 + m] = t.z; At[(kk + 3) * 128 + m] = t.w;
        }
        #pragma unroll
        for (int i = 0; i < 2; i++) {
            int f = i * 1024 + tid * 4; int kk = f >> 6, d0 = f & 63;
            *(float4*)&Vs[kk * 64 + d0] =
                *(const float4*)&g_v[((size_t)bh * L_ + kbase + kt + kk) * D_ + d0];
        }
        __syncthreads();
        for (int k = 0; k < 32; k++) {
            float4 a0 = *(const float4*)&At[k * 128 + rt * 8];
            float4 a1 = *(const float4*)&At[k * 128 + rt * 8 + 4];
            float4 b  = *(const float4*)&Vs[k * 64 + ct * 4];
            float av[8] = {a0.x, a0.y, a0.z, a0.w, a1.x, a1.y, a1.z, a1.w};
            #pragma unroll
            for (int i = 0; i < 8; i++) {
                acc[i][0] += av[i] * b.x; acc[i][1] += av[i] * b.y;
                acc[i][2] += av[i] * b.z; acc[i][3] += av[i] * b.w;
            }
        }
    }
    #pragma unroll
    for (int i = 0; i < 8; i++) {
        float4 t = make_float4(acc[i][0], acc[i][1], acc[i][2], acc[i][3]);
        *(float4*)&g_k3v_part[((size_t)(s * 64 + bh) * 128 + rt * 8 + i) * 64 + ct * 4] = t;
    }
}

__global__ void k3v_reduce_kernel()
{
    int idx = blockIdx.x * blockDim.x + threadIdx.x;  // 524288
    float s = 0.f;
    #pragma unroll
    for (int p = 0; p < 8; p++) s += g_k3v_part[(size_t)p * 524288 + idx];
    g_k3v[idx] = s;
}

// =====================================================================
// y2 = inv(g_Va) @ k3v  per head
// =====================================================================
__global__ __launch_bounds__(256) void y2_kernel()
{
    extern __shared__ float sm[];
    float* At = sm;           // [k=128][r=128]
    float* Bs = sm + 16384;   // [k=128][d=64]
    int bh = blockIdx.x, tid = threadIdx.x;
    const float* inv = g_Va + bh * 16384;
    const float* kv  = g_k3v + bh * 8192;

    #pragma unroll
    for (int i = 0; i < 16; i++) {
        int f = i * 1024 + tid * 4; int r = f >> 7, k0 = f & 127;
        float4 t = *(const float4*)&inv[f];
        At[(k0 + 0) * 128 + r] = t.x; At[(k0 + 1) * 128 + r] = t.y;
        At[(k0 + 2) * 128 + r] = t.z; At[(k0 + 3) * 128 + r] = t.w;
    }
    #pragma unroll
    for (int i = 0; i < 8; i++) {
        int f = i * 1024 + tid * 4;
        *(float4*)&Bs[f] = *(const float4*)&kv[f];
    }
    __syncthreads();

    int rt = tid >> 4, ct = tid & 15;
    float acc[8][4] = {};
    for (int k = 0; k < 128; k++) {
        float4 a0 = *(const float4*)&At[k * 128 + rt * 8];
        float4 a1 = *(const float4*)&At[k * 128 + rt * 8 + 4];
        float4 b  = *(const float4*)&Bs[k * 64 + ct * 4];
        float av[8] = {a0.x, a0.y, a0.z, a0.w, a1.x, a1.y, a1.z, a1.w};
        #pragma unroll
        for (int i = 0; i < 8; i++) {
            acc[i][0] += av[i] * b.x; acc[i][1] += av[i] * b.y;
            acc[i][2] += av[i] * b.z; acc[i][3] += av[i] * b.w;
        }
    }
    #pragma unroll
    for (int i = 0; i < 8; i++) {
        float4 t = make_float4(acc[i][0], acc[i][1], acc[i][2], acc[i][3]);
        *(float4*)&g_y2[(size_t)bh * 8192 + (rt * 8 + i) * 64 + ct * 4] = t;
    }
}

// =====================================================================
// X1 = kernel_1 @ y2 per head, written as bf16 hi/lo split straight into
// g_ah/g_al in [b,l,h*64+d] layout (A operand of the output projection).
// =====================================================================
__global__ __launch_bounds__(256) void x1_kernel()
{
    extern __shared__ float sm[];
    float* At = sm;           // [m=128][l=128]
    float* Bs = sm + 16384;   // [m=128][d=64]
    int bh = blockIdx.y, l0 = blockIdx.x * 128, tid = threadIdx.x;

    #pragma unroll
    for (int i = 0; i < 16; i++) {
        int f = i * 1024 + tid * 4; int r = f >> 7, m0 = f & 127;
        float4 t = *(const float4*)&g_k1[(size_t)bh * (L_ * M_) + (size_t)(l0 + r) * 128 + m0];
        At[(m0 + 0) * 128 + r] = t.x; At[(m0 + 1) * 128 + r] = t.y;
        At[(m0 + 2) * 128 + r] = t.z; At[(m0 + 3) * 128 + r] = t.w;
    }
    #pragma unroll
    for (int i = 0; i < 8; i++) {
        int f = i * 1024 + tid * 4;
        *(float4*)&Bs[f] = *(const float4*)&g_y2[(size_t)bh * 8192 + f];
    }
    __syncthreads();

    int rt = tid >> 4, ct = tid & 15;
    float acc[8][4] = {};
    for (int k = 0; k < 128; k++) {
        float4 a0 = *(const float4*)&At[k * 128 + rt * 8];
        float4 a1 = *(const float4*)&At[k * 128 + rt * 8 + 4];
        float4 b  = *(const float4*)&Bs[k * 64 + ct * 4];
        float av[8] = {a0.x, a0.y, a0.z, a0.w, a1.x, a1.y, a1.z, a1.w};
        #pragma unroll
        for (int i = 0; i < 8; i++) {
            acc[i][0] += av[i] * b.x; acc[i][1] += av[i] * b.y;
            acc[i][2] += av[i] * b.z; acc[i][3] += av[i] * b.w;
        }
    }
    int b = bh >> 4, h = bh & 15;
    #pragma unroll
    for (int i = 0; i < 8; i++) {
        int l = l0 + rt * 8 + i;
        size_t base = ((size_t)(b * L_ + l)) * DM_ + h * 64 + ct * 4;
        __nv_bfloat16 hi[4], lo[4];
        #pragma unroll
        for (int t = 0; t < 4; t++) {
            float v = acc[i][t];
            hi[t] = __float2bfloat16(v);
            lo[t] = __float2bfloat16(v - __bfloat162float(hi[t]));
        }
        *(uint2*)&g_ah[base] = *(uint2*)hi;
        *(uint2*)&g_al[base] = *(uint2*)lo;
    }
}

// =====================================================================
// launch
// =====================================================================
extern "C" void kernel_launch(void* const* d_in, const int* in_sizes, int n_in,
                              void* d_out, int out_size)
{
    const float* queries = (const float*)d_in[0];
    const float* keys    = (const float*)d_in[1];
    const float* values  = (const float*)d_in[2];
    const float* Wq = (const float*)d_in[3];
    const float* bq = (const float*)d_in[4];
    const float* Wk = (const float*)d_in[5];
    const float* bk = (const float*)d_in[6];
    const float* Wv = (const float*)d_in[7];
    const float* bv = (const float*)d_in[8];
    const float* Wo = (const float*)d_in[9];
    const float* bo = (const float*)d_in[10];
    float* out = (float*)d_out;

    cudaFuncSetAttribute(gemm_mma_kernel, cudaFuncAttributeMaxDynamicSharedMemorySize, 81920);
    cudaFuncSetAttribute(k1_kernel,      cudaFuncAttributeMaxDynamicSharedMemorySize, 57344);
    cudaFuncSetAttribute(k3score_kernel, cudaFuncAttributeMaxDynamicSharedMemorySize, 65536);
    cudaFuncSetAttribute(k2_kernel,      cudaFuncAttributeMaxDynamicSharedMemorySize, 131072);
    cudaFuncSetAttribute(bmm_kernel,     cudaFuncAttributeMaxDynamicSharedMemorySize, 81920);
    cudaFuncSetAttribute(y2_kernel,      cudaFuncAttributeMaxDynamicSharedMemorySize, 98304);
    cudaFuncSetAttribute(x1_kernel,      cudaFuncAttributeMaxDynamicSharedMemorySize, 98304);

    __nv_bfloat16 *ahp = nullptr, *alp = nullptr;
    cudaGetSymbolAddress((void**)&ahp, g_ah);
    cudaGetSymbolAddress((void**)&alp, g_al);

    dim3 wt_grid(32, 32), wt_blk(32, 8);
    dim3 gemm_grid(8, 128);   // n-tiles x m-tiles

    // Q projection
    conv_wt_kernel<<<wt_grid, wt_blk>>>(Wq);
    conv_act_kernel<<<16384, 256>>>(queries);
    gemm_mma_kernel<<<gemm_grid, 256, 81920>>>(ahp, alp, bq, nullptr, 0);
    // K projection
    conv_wt_kernel<<<wt_grid, wt_blk>>>(Wk);
    conv_act_kernel<<<16384, 256>>>(keys);
    gemm_mma_kernel<<<gemm_grid, 256, 81920>>>(ahp, alp, bk, nullptr, 1);
    // V projection
    conv_wt_kernel<<<wt_grid, wt_blk>>>(Wv);
    conv_act_kernel<<<16384, 256>>>(values);
    gemm_mma_kernel<<<gemm_grid, 256, 81920>>>(ahp, alp, bv, nullptr, 2);

    // landmark pooling
    pool_kernel<<<2048, 256>>>();

    // kernel_1 (fused score+softmax over 128)
    k1_kernel<<<dim3(128, 64), 256, 57344>>>();

    // kernel_3 scores + softmax over 4096
    k3score_kernel<<<dim3(32, 64), 256, 65536>>>();
    softmax4096_kernel<<<8192, 256>>>();

    // kernel_2 + Newton-Schulz pseudo-inverse
    k2_kernel<<<64, 256, 131072>>>();
    vinit_kernel<<<64, 256>>>();
    int cur = 4, nxt = 5;   // g_Va / g_Vb
    for (int it = 0; it < 6; it++) {
        bmm_kernel<<<dim3(4, 64), 256, 81920>>>(0,   cur, 0,   1,   1.0f,  0.0f);  // P  = K@V
        bmm_kernel<<<dim3(4, 64), 256, 81920>>>(1,   1,   1,   2,  -1.0f,  7.0f);  // M1 = 7P - P@P
        bmm_kernel<<<dim3(4, 64), 256, 81920>>>(1,   2,   1,   3,  -1.0f, 15.0f);  // M2 = 15P - P@M1
        bmm_kernel<<<dim3(4, 64), 256, 81920>>>(cur, 3,   cur, nxt, -0.25f, 3.25f);// V' = .25(13V - V@M2)
        int t = cur; cur = nxt; nxt = t;
    }
    // after 6 iterations cur == 4 (g_Va) holds the pseudo-inverse

    // kernel_3 @ v  (split-K 8 + reduce)
    k3v_kernel<<<dim3(8, 64), 256, 24576>>>();
    k3v_reduce_kernel<<<2048, 256>>>();

    // y2 = inv @ k3v ; X1 = kernel_1 @ y2 -> g_ah/g_al (bf16 split, [b,l,h*64+d])
    y2_kernel<<<64, 256, 98304>>>();
    x1_kernel<<<dim3(32, 64), 256, 98304>>>();

    // output projection (A = x split, W = Wo)
    conv_wt_kernel<<<wt_grid, wt_blk>>>(Wo);
    gemm_mma_kernel<<<gemm_grid, 256, 81920>>>(ahp, alp, bo, out, 3);
}

// round 5
// speedup vs baseline: 2.1285x; 1.2521x over previous
#include <cuda_runtime.h>
#include <cuda_bf16.h>
#include <cstdint>

// ---------------- problem constants ----------------
#define B_    4
#define L_    4096
#define DM_   1024
#define H_    16
#define D_    64
#define M_    128
#define BH_   64          // B*H
#define SEG_  32          // L/M
#define NTOK_ 16384       // B*L

// single dynamic-smem symbol for the whole TU
extern __shared__ char dynsm[];

// ---------------- scratch (device globals; no allocations allowed) ----------------
__device__ float g_Ql[BH_ * M_ * D_];          // fp32 landmarks (for k2)
__device__ float g_Kl[BH_ * M_ * D_];
__device__ float g_k3[(size_t)BH_ * M_ * L_];  // raw scores fp32
__device__ float g_k2[BH_ * M_ * M_];
__device__ float g_P [BH_ * M_ * M_];
__device__ float g_M1[BH_ * M_ * M_];
__device__ float g_M2[BH_ * M_ * M_];
__device__ float g_Va[BH_ * M_ * M_];
__device__ float g_Vb[BH_ * M_ * M_];
__device__ float g_k3v_part[4 * BH_ * M_ * D_];
__device__ float g_k3v[BH_ * M_ * D_];

// bf16 split buffers
__device__ __align__(16) __nv_bfloat16 g_ah[(size_t)NTOK_ * DM_];   // gemm A hi
__device__ __align__(16) __nv_bfloat16 g_al[(size_t)NTOK_ * DM_];   // gemm A lo
__device__ __align__(16) __nv_bfloat16 g_wh[DM_ * DM_];             // W^T hi [n][k]
__device__ __align__(16) __nv_bfloat16 g_wl[DM_ * DM_];
__device__ __align__(16) __nv_bfloat16 g_qh[(size_t)BH_ * L_ * D_]; // q split [bh][l][d]
__device__ __align__(16) __nv_bfloat16 g_ql[(size_t)BH_ * L_ * D_];
__device__ __align__(16) __nv_bfloat16 g_kh[(size_t)BH_ * L_ * D_];
__device__ __align__(16) __nv_bfloat16 g_kl[(size_t)BH_ * L_ * D_];
__device__ __align__(16) __nv_bfloat16 g_vh[(size_t)BH_ * L_ * D_];
__device__ __align__(16) __nv_bfloat16 g_vl[(size_t)BH_ * L_ * D_];
__device__ __align__(16) __nv_bfloat16 g_Qlh[BH_ * M_ * D_];
__device__ __align__(16) __nv_bfloat16 g_Qll[BH_ * M_ * D_];
__device__ __align__(16) __nv_bfloat16 g_Klh[BH_ * M_ * D_];
__device__ __align__(16) __nv_bfloat16 g_Kll[BH_ * M_ * D_];
__device__ __align__(16) __nv_bfloat16 g_k1h[(size_t)BH_ * L_ * M_]; // kernel_1 split [bh][l][m]
__device__ __align__(16) __nv_bfloat16 g_k1l[(size_t)BH_ * L_ * M_];
__device__ __align__(16) __nv_bfloat16 g_s3h[(size_t)BH_ * M_ * L_]; // softmaxed k3 split [bh][m][l]
__device__ __align__(16) __nv_bfloat16 g_s3l[(size_t)BH_ * M_ * L_];
__device__ __align__(16) __nv_bfloat16 g_y2th[BH_ * D_ * M_];        // y2^T split [bh][d][m]
__device__ __align__(16) __nv_bfloat16 g_y2tl[BH_ * D_ * M_];

// =====================================================================
// PTX helpers (baseline set only: mma.sync / ldmatrix / cp.async)
// =====================================================================
__device__ __forceinline__ uint32_t smem_to_u32(const void* p) {
    uint32_t a;
    asm("{ .reg .u64 t; cvta.to.shared.u64 t, %1; cvt.u32.u64 %0, t; }" : "=r"(a) : "l"(p));
    return a;
}
__device__ __forceinline__ void ldsm4(uint32_t* r, uint32_t addr) {
    asm volatile("ldmatrix.sync.aligned.m8n8.x4.shared.b16 {%0,%1,%2,%3}, [%4];"
        : "=r"(r[0]), "=r"(r[1]), "=r"(r[2]), "=r"(r[3]) : "r"(addr));
}
__device__ __forceinline__ void ldsm4t(uint32_t* r, uint32_t addr) {
    asm volatile("ldmatrix.sync.aligned.m8n8.x4.trans.shared.b16 {%0,%1,%2,%3}, [%4];"
        : "=r"(r[0]), "=r"(r[1]), "=r"(r[2]), "=r"(r[3]) : "r"(addr));
}
__device__ __forceinline__ void mma16816(float* d, const uint32_t* a, const uint32_t* b) {
    asm volatile("mma.sync.aligned.m16n8k16.row.col.f32.bf16.bf16.f32 "
        "{%0,%1,%2,%3}, {%4,%5,%6,%7}, {%8,%9}, {%0,%1,%2,%3};"
        : "+f"(d[0]), "+f"(d[1]), "+f"(d[2]), "+f"(d[3])
        : "r"(a[0]), "r"(a[1]), "r"(a[2]), "r"(a[3]), "r"(b[0]), "r"(b[1]));
}
#define CP_ASYNC16(dst, src) \
    asm volatile("cp.async.cg.shared.global [%0], [%1], 16;" :: "r"(dst), "l"(src))
#define CP_COMMIT()  asm volatile("cp.async.commit_group;" ::: "memory")
#define CP_WAIT(n)   asm volatile("cp.async.wait_group %0;" :: "n"(n) : "memory")

__device__ __forceinline__ void split_bf16(float v, __nv_bfloat16& h, __nv_bfloat16& l) {
    h = __float2bfloat16(v);
    l = __float2bfloat16(v - __bfloat162float(h));
}

// =====================================================================
// conversion kernels (fp32 -> bf16 hi/lo split)
// =====================================================================
__global__ void conv_act_kernel(const float* __restrict__ src)
{
    size_t i4 = (size_t)blockIdx.x * 256 + threadIdx.x;
    float4 v = *(const float4*)&src[i4 * 4];
    __nv_bfloat16 h[4], l[4];
    float a[4] = {v.x, v.y, v.z, v.w};
    #pragma unroll
    for (int i = 0; i < 4; i++) split_bf16(a[i], h[i], l[i]);
    *(uint2*)&g_ah[i4 * 4] = *(uint2*)h;
    *(uint2*)&g_al[i4 * 4] = *(uint2*)l;
}

__global__ void conv_wt_kernel(const float* __restrict__ W)
{
    __shared__ float t[32][33];
    int x = blockIdx.x * 32 + threadIdx.x;
    int y = blockIdx.y * 32 + threadIdx.y;
    #pragma unroll
    for (int j = 0; j < 32; j += 8) t[threadIdx.y + j][threadIdx.x] = W[(size_t)(y + j) * 1024 + x];
    __syncthreads();
    int xo = blockIdx.y * 32 + threadIdx.x;
    int yo = blockIdx.x * 32 + threadIdx.y;
    #pragma unroll
    for (int j = 0; j < 32; j += 8) {
        float v = t[threadIdx.x][threadIdx.y + j];
        __nv_bfloat16 h, l; split_bf16(v, h, l);
        g_wh[(size_t)(yo + j) * 1024 + xo] = h;
        g_wl[(size_t)(yo + j) * 1024 + xo] = l;
    }
}

// =====================================================================
// main projection GEMM (epilogue writes bf16 split for q/k/v; fp32 for mode 3)
// =====================================================================
#define PITCH   40
#define TSZ     (128 * PITCH * 2)
#define BUFSZ   (4 * TSZ)
#define OFF_AH  0
#define OFF_AL  (1 * TSZ)
#define OFF_BH  (2 * TSZ)
#define OFF_BL  (3 * TSZ)

__global__ __launch_bounds__(256) void gemm_mma_kernel(
    const __nv_bfloat16* __restrict__ Ah, const __nv_bfloat16* __restrict__ Al,
    const float* __restrict__ bias, float* __restrict__ outp, int mode)
{
    char* smem = dynsm;
    const uint32_t sbase = smem_to_u32(smem);

    const int tid  = threadIdx.x;
    const int lane = tid & 31;
    const int w    = tid >> 5;
    const int wm   = w >> 2;
    const int wn   = w & 3;
    const int n0 = blockIdx.x * 128;
    const int m0 = blockIdx.y * 128;

    float acc[4][4][4];
    #pragma unroll
    for (int i = 0; i < 4; i++)
        #pragma unroll
        for (int j = 0; j < 4; j++)
            #pragma unroll
            for (int t = 0; t < 4; t++) acc[i][j][t] = 0.f;

    auto load_chunk = [&](int c, int buf) {
        const int k0 = c * 32;
        const uint32_t sb = sbase + buf * BUFSZ;
        #pragma unroll
        for (int i = 0; i < 8; i++) {
            int q = tid + i * 256;
            int arr = q >> 9;
            int r   = (q >> 2) & 127;
            int c4  = q & 3;
            uint32_t dst = sb + arr * TSZ + r * 80 + c4 * 16;
            const __nv_bfloat16* src;
            if      (arr == 0) src = &Ah  [(size_t)(m0 + r) * 1024 + k0 + c4 * 8];
            else if (arr == 1) src = &Al  [(size_t)(m0 + r) * 1024 + k0 + c4 * 8];
            else if (arr == 2) src = &g_wh[(size_t)(n0 + r) * 1024 + k0 + c4 * 8];
            else               src = &g_wl[(size_t)(n0 + r) * 1024 + k0 + c4 * 8];
            CP_ASYNC16(dst, src);
        }
        CP_COMMIT();
    };

    auto compute_chunk = [&](int buf) {
        const uint32_t S = sbase + buf * BUFSZ;
        #pragma unroll
        for (int k16 = 0; k16 < 2; k16++) {
            const uint32_t kb = (uint32_t)(k16 * 32);
            uint32_t af[2][4][4];
            #pragma unroll
            for (int term = 0; term < 2; term++) {
                uint32_t base = S + (term ? OFF_AL : OFF_AH);
                #pragma unroll
                for (int mt = 0; mt < 4; mt++) {
                    uint32_t addr = base
                        + (uint32_t)((wm * 64 + mt * 16 + (lane & 15)) * 80)
                        + kb + (uint32_t)((lane >> 4) * 16);
                    ldsm4(af[term][mt], addr);
                }
            }
            uint32_t bf[2][2][4];
            #pragma unroll
            for (int term = 0; term < 2; term++) {
                uint32_t base = S + (term ? OFF_BL : OFF_BH);
                #pragma unroll
                for (int np = 0; np < 2; np++) {
                    uint32_t nrow = (uint32_t)(wn * 32 + np * 16 + ((lane >> 4) * 8) + (lane & 7));
                    uint32_t addr = base + nrow * 80 + kb + (uint32_t)(((lane >> 3) & 1) * 16);
                    ldsm4(bf[term][np], addr);
                }
            }
            #pragma unroll
            for (int mt = 0; mt < 4; mt++) {
                #pragma unroll
                for (int nt = 0; nt < 4; nt++) {
                    float* d = acc[mt][nt];
                    const uint32_t* bh_ = &bf[0][nt >> 1][(nt & 1) * 2];
                    const uint32_t* bl_ = &bf[1][nt >> 1][(nt & 1) * 2];
                    mma16816(d, af[0][mt], bh_);
                    mma16816(d, af[0][mt], bl_);
                    mma16816(d, af[1][mt], bh_);
                }
            }
        }
    };

    load_chunk(0, 0);
    #pragma unroll 1
    for (int c = 0; c < 32; c++) {
        if (c + 1 < 32) {
            load_chunk(c + 1, (c + 1) & 1);
            CP_WAIT(1);
        } else {
            CP_WAIT(0);
        }
        __syncthreads();
        compute_chunk(c & 1);
        __syncthreads();
    }

    #pragma unroll
    for (int mt = 0; mt < 4; mt++) {
        #pragma unroll
        for (int nt = 0; nt < 4; nt++) {
            int c = n0 + wn * 32 + nt * 8 + (lane & 3) * 2;
            float b0 = bias[c], b1 = bias[c + 1];
            #pragma unroll
            for (int half = 0; half < 2; half++) {
                int r = m0 + wm * 64 + mt * 16 + (lane >> 2) + half * 8;
                float vx = acc[mt][nt][half * 2 + 0] + b0;
                float vy = acc[mt][nt][half * 2 + 1] + b1;
                if (mode == 3) {
                    float2 t = {vx, vy};
                    *(float2*)&outp[(size_t)r * 1024 + c] = t;
                } else {
                    __nv_bfloat16* dh = (mode == 0) ? g_qh : ((mode == 1) ? g_kh : g_vh);
                    __nv_bfloat16* dl = (mode == 0) ? g_ql : ((mode == 1) ? g_kl : g_vl);
                    int b = r >> 12, l = r & 4095;
                    int h = c >> 6, d = c & 63;
                    size_t o = (((size_t)(b * 16 + h) * 4096) + l) * 64 + d;
                    __nv_bfloat16 hp[2], lp[2];
                    split_bf16(vx, hp[0], lp[0]);
                    split_bf16(vy, hp[1], lp[1]);
                    *(uint32_t*)&dh[o] = *(uint32_t*)hp;
                    *(uint32_t*)&dl[o] = *(uint32_t*)lp;
                }
            }
        }
    }
}

// =====================================================================
// landmark pooling from split q/k; writes fp32 + split landmarks
// =====================================================================
__global__ void pool_kernel()
{
    int idx = blockIdx.x * blockDim.x + threadIdx.x;   // BH*M*D
    int d  = idx & 63;
    int m  = (idx >> 6) & 127;
    int bh = idx >> 13;
    size_t base = ((size_t)bh * L_ + m * SEG_) * D_ + d;
    float sq = 0.f, sk = 0.f;
    #pragma unroll
    for (int s = 0; s < SEG_; s++) {
        sq += __bfloat162float(g_qh[base + s * D_]) + __bfloat162float(g_ql[base + s * D_]);
        sk += __bfloat162float(g_kh[base + s * D_]) + __bfloat162float(g_kl[base + s * D_]);
    }
    float mq = sq * (1.f / SEG_), mk = sk * (1.f / SEG_);
    g_Ql[idx] = mq; g_Kl[idx] = mk;
    __nv_bfloat16 h, l;
    split_bf16(mq, h, l); g_Qlh[idx] = h; g_Qll[idx] = l;
    split_bf16(mk, h, l); g_Klh[idx] = h; g_Kll[idx] = l;
}

// =====================================================================
// k1: C[128 tok][128 lm] = q_blk @ Kl^T (split mma) + fused softmax -> split bf16
// smem: Ah 0 | Al 18432 | Bh 36864 | Bl 55296  (pitch 144 B); dyn smem 73728
// =====================================================================
__global__ __launch_bounds__(256) void k1_mma_kernel()
{
    char* sm = dynsm;
    const uint32_t sb = smem_to_u32(sm);
    int bh = blockIdx.y, l0 = blockIdx.x * 128, tid = threadIdx.x;
    int lane = tid & 31, w = tid >> 5;

    {
        const __nv_bfloat16* qh = g_qh + ((size_t)bh * L_ + l0) * D_;
        const __nv_bfloat16* ql = g_ql + ((size_t)bh * L_ + l0) * D_;
        const __nv_bfloat16* kh = g_Klh + bh * (M_ * D_);
        const __nv_bfloat16* kl = g_Kll + bh * (M_ * D_);
        #pragma unroll
        for (int i = 0; i < 4; i++) {
            int q = tid + i * 256;              // 0..1023
            int row = q >> 3, c8 = q & 7;
            uint32_t so = (uint32_t)(row * 144 + c8 * 16);
            size_t go = (size_t)row * 64 + c8 * 8;
            *(uint4*)(sm + 0     + so) = *(const uint4*)&qh[go];
            *(uint4*)(sm + 18432 + so) = *(const uint4*)&ql[go];
            *(uint4*)(sm + 36864 + so) = *(const uint4*)&kh[go];
            *(uint4*)(sm + 55296 + so) = *(const uint4*)&kl[go];
        }
    }
    __syncthreads();

    int wm = w >> 2, wn = w & 3;
    float acc[4][4][4];
    #pragma unroll
    for (int i = 0; i < 4; i++)
        #pragma unroll
        for (int j = 0; j < 4; j++)
            #pragma unroll
            for (int t = 0; t < 4; t++) acc[i][j][t] = 0.f;

    #pragma unroll
    for (int k16 = 0; k16 < 4; k16++) {
        uint32_t af[2][4][4];
        #pragma unroll
        for (int term = 0; term < 2; term++)
            #pragma unroll
            for (int mt = 0; mt < 4; mt++) {
                uint32_t addr = sb + term * 18432
                    + (uint32_t)((wm * 64 + mt * 16 + (lane & 15)) * 144)
                    + (uint32_t)(k16 * 32) + (uint32_t)((lane >> 4) * 16);
                ldsm4(af[term][mt], addr);
            }
        uint32_t bf[2][2][4];
        #pragma unroll
        for (int term = 0; term < 2; term++)
            #pragma unroll
            for (int np = 0; np < 2; np++) {
                uint32_t nrow = (uint32_t)(wn * 32 + np * 16 + ((lane >> 4) * 8) + (lane & 7));
                uint32_t addr = sb + 36864 + term * 18432 + nrow * 144
                    + (uint32_t)(k16 * 32) + (uint32_t)(((lane >> 3) & 1) * 16);
                ldsm4(bf[term][np], addr);
            }
        #pragma unroll
        for (int mt = 0; mt < 4; mt++)
            #pragma unroll
            for (int nt = 0; nt < 4; nt++) {
                float* d = acc[mt][nt];
                const uint32_t* bh_ = &bf[0][nt >> 1][(nt & 1) * 2];
                const uint32_t* bl_ = &bf[1][nt >> 1][(nt & 1) * 2];
                mma16816(d, af[0][mt], bh_);
                mma16816(d, af[0][mt], bl_);
                mma16816(d, af[1][mt], bh_);
            }
    }
    __syncthreads();

    float* S = (float*)sm;
    #pragma unroll
    for (int mt = 0; mt < 4; mt++)
        #pragma unroll
        for (int nt = 0; nt < 4; nt++)
            #pragma unroll
            for (int half = 0; half < 2; half++) {
                int row = wm * 64 + mt * 16 + (lane >> 2) + half * 8;
                int col = wn * 32 + nt * 8 + (lane & 3) * 2;
                S[row * 128 + col]     = acc[mt][nt][half * 2 + 0];
                S[row * 128 + col + 1] = acc[mt][nt][half * 2 + 1];
            }
    __syncthreads();

    for (int rr = 0; rr < 16; rr++) {
        int row = w * 16 + rr;
        float x0 = S[row * 128 + lane],      x1 = S[row * 128 + lane + 32];
        float x2 = S[row * 128 + lane + 64], x3 = S[row * 128 + lane + 96];
        float mx = fmaxf(fmaxf(x0, x1), fmaxf(x2, x3));
        #pragma unroll
        for (int o = 16; o; o >>= 1) mx = fmaxf(mx, __shfl_xor_sync(0xffffffffu, mx, o));
        float e0 = __expf(x0 - mx), e1 = __expf(x1 - mx);
        float e2 = __expf(x2 - mx), e3 = __expf(x3 - mx);
        float s = e0 + e1 + e2 + e3;
        #pragma unroll
        for (int o = 16; o; o >>= 1) s += __shfl_xor_sync(0xffffffffu, s, o);
        float inv = 1.f / s;
        size_t ob = ((size_t)bh * L_ + l0 + row) * 128;
        float vv[4] = {e0 * inv, e1 * inv, e2 * inv, e3 * inv};
        #pragma unroll
        for (int j = 0; j < 4; j++) {
            __nv_bfloat16 h, l; split_bf16(vv[j], h, l);
            g_k1h[ob + lane + 32 * j] = h;
            g_k1l[ob + lane + 32 * j] = l;
        }
    }
}

// =====================================================================
// k3 scores: C[m=128][l=128 blk] = Ql @ k_blk^T (split mma) -> raw fp32 g_k3
// dyn smem 73728
// =====================================================================
__global__ __launch_bounds__(256) void k3score_mma_kernel()
{
    char* sm = dynsm;
    const uint32_t sb = smem_to_u32(sm);
    int bh = blockIdx.y, l0 = blockIdx.x * 128, tid = threadIdx.x;
    int lane = tid & 31, w = tid >> 5;

    {
        const __nv_bfloat16* ah = g_Qlh + bh * (M_ * D_);
        const __nv_bfloat16* al = g_Qll + bh * (M_ * D_);
        const __nv_bfloat16* bhp = g_kh + ((size_t)bh * L_ + l0) * D_;
        const __nv_bfloat16* blp = g_kl + ((size_t)bh * L_ + l0) * D_;
        #pragma unroll
        for (int i = 0; i < 4; i++) {
            int q = tid + i * 256;
            int row = q >> 3, c8 = q & 7;
            uint32_t so = (uint32_t)(row * 144 + c8 * 16);
            size_t go = (size_t)row * 64 + c8 * 8;
            *(uint4*)(sm + 0     + so) = *(const uint4*)&ah[go];
            *(uint4*)(sm + 18432 + so) = *(const uint4*)&al[go];
            *(uint4*)(sm + 36864 + so) = *(const uint4*)&bhp[go];
            *(uint4*)(sm + 55296 + so) = *(const uint4*)&blp[go];
        }
    }
    __syncthreads();

    int wm = w >> 2, wn = w & 3;
    float acc[4][4][4];
    #pragma unroll
    for (int i = 0; i < 4; i++)
        #pragma unroll
        for (int j = 0; j < 4; j++)
            #pragma unroll
            for (int t = 0; t < 4; t++) acc[i][j][t] = 0.f;

    #pragma unroll
    for (int k16 = 0; k16 < 4; k16++) {
        uint32_t af[2][4][4];
        #pragma unroll
        for (int term = 0; term < 2; term++)
            #pragma unroll
            for (int mt = 0; mt < 4; mt++) {
                uint32_t addr = sb + term * 18432
                    + (uint32_t)((wm * 64 + mt * 16 + (lane & 15)) * 144)
                    + (uint32_t)(k16 * 32) + (uint32_t)((lane >> 4) * 16);
                ldsm4(af[term][mt], addr);
            }
        uint32_t bf[2][2][4];
        #pragma unroll
        for (int term = 0; term < 2; term++)
            #pragma unroll
            for (int np = 0; np < 2; np++) {
                uint32_t nrow = (uint32_t)(wn * 32 + np * 16 + ((lane >> 4) * 8) + (lane & 7));
                uint32_t addr = sb + 36864 + term * 18432 + nrow * 144
                    + (uint32_t)(k16 * 32) + (uint32_t)(((lane >> 3) & 1) * 16);
                ldsm4(bf[term][np], addr);
            }
        #pragma unroll
        for (int mt = 0; mt < 4; mt++)
            #pragma unroll
            for (int nt = 0; nt < 4; nt++) {
                float* d = acc[mt][nt];
                const uint32_t* bh_ = &bf[0][nt >> 1][(nt & 1) * 2];
                const uint32_t* bl_ = &bf[1][nt >> 1][(nt & 1) * 2];
                mma16816(d, af[0][mt], bh_);
                mma16816(d, af[0][mt], bl_);
                mma16816(d, af[1][mt], bh_);
            }
    }

    float* o = g_k3 + (size_t)bh * M_ * L_;
    #pragma unroll
    for (int mt = 0; mt < 4; mt++)
        #pragma unroll
        for (int nt = 0; nt < 4; nt++)
            #pragma unroll
            for (int half = 0; half < 2; half++) {
                int m_r = wm * 64 + mt * 16 + (lane >> 2) + half * 8;
                int l_c = l0 + wn * 32 + nt * 8 + (lane & 3) * 2;
                float2 t = {acc[mt][nt][half * 2 + 0], acc[mt][nt][half * 2 + 1]};
                *(float2*)&o[(size_t)m_r * L_ + l_c] = t;
            }
}

// =====================================================================
// row softmax over 4096; reads fp32 g_k3, writes split bf16 g_s3
// =====================================================================
__global__ __launch_bounds__(256) void softmax4096_kernel()
{
    size_t row = blockIdx.x;
    const float* p = g_k3 + row * 4096;
    int tid = threadIdx.x;
    float v[16];
    float mx = -1e30f;
    #pragma unroll
    for (int i = 0; i < 4; i++) {
        float4 t = *(const float4*)&p[i * 1024 + tid * 4];
        v[i * 4 + 0] = t.x; v[i * 4 + 1] = t.y; v[i * 4 + 2] = t.z; v[i * 4 + 3] = t.w;
        mx = fmaxf(mx, fmaxf(fmaxf(t.x, t.y), fmaxf(t.z, t.w)));
    }
    __shared__ float smx[8], ssm[8], sres;
    #pragma unroll
    for (int o = 16; o; o >>= 1) mx = fmaxf(mx, __shfl_xor_sync(0xffffffffu, mx, o));
    if ((tid & 31) == 0) smx[tid >> 5] = mx;
    __syncthreads();
    if (tid == 0) {
        float m = smx[0];
        #pragma unroll
        for (int i = 1; i < 8; i++) m = fmaxf(m, smx[i]);
        sres = m;
    }
    __syncthreads();
    float MX = sres;
    float s = 0.f;
    #pragma unroll
    for (int i = 0; i < 16; i++) { v[i] = __expf(v[i] - MX); s += v[i]; }
    #pragma unroll
    for (int o = 16; o; o >>= 1) s += __shfl_xor_sync(0xffffffffu, s, o);
    if ((tid & 31) == 0) ssm[tid >> 5] = s;
    __syncthreads();
    if (tid == 0) {
        float t = 0.f;
        #pragma unroll
        for (int i = 0; i < 8; i++) t += ssm[i];
        sres = 1.f / t;
    }
    __syncthreads();
    float inv = sres;
    #pragma unroll
    for (int i = 0; i < 4; i++) {
        __nv_bfloat16 hh[4], ll[4];
        #pragma unroll
        for (int t = 0; t < 4; t++) split_bf16(v[i * 4 + t] * inv, hh[t], ll[t]);
        *(uint2*)&g_s3h[row * 4096 + i * 1024 + tid * 4] = *(uint2*)hh;
        *(uint2*)&g_s3l[row * 4096 + i * 1024 + tid * 4] = *(uint2*)ll;
    }
}

// =====================================================================
// kernel_2 = softmax(Q_l @ K_l^T) fused (fp32, tiny). block per head.
// =====================================================================
__global__ __launch_bounds__(256) void k2_kernel()
{
    float* sm = (float*)dynsm;
    float* Qlt = sm;
    float* Klt = sm + 8192;
    float* S   = sm + 16384;
    int bh = blockIdx.x, tid = threadIdx.x;

    const float* Ql = g_Ql + bh * 8192;
    const float* Kl = g_Kl + bh * 8192;
    #pragma unroll
    for (int i = 0; i < 8; i++) {
        int f = i * 1024 + tid * 4; int m = f >> 6, d0 = f & 63;
        float4 tq = *(const float4*)&Ql[f];
        float4 tk = *(const float4*)&Kl[f];
        Qlt[(d0 + 0) * 128 + m] = tq.x; Qlt[(d0 + 1) * 128 + m] = tq.y;
        Qlt[(d0 + 2) * 128 + m] = tq.z; Qlt[(d0 + 3) * 128 + m] = tq.w;
        Klt[(d0 + 0) * 128 + m] = tk.x; Klt[(d0 + 1) * 128 + m] = tk.y;
        Klt[(d0 + 2) * 128 + m] = tk.z; Klt[(d0 + 3) * 128 + m] = tk.w;
    }
    __syncthreads();

    int tm = tid >> 4, tn = tid & 15;
    float acc[8][8] = {};
    for (int d = 0; d < 64; d++) {
        float4 a0 = *(const float4*)&Qlt[d * 128 + tm * 8];
        float4 a1 = *(const float4*)&Qlt[d * 128 + tm * 8 + 4];
        float4 b0 = *(const float4*)&Klt[d * 128 + tn * 8];
        float4 b1 = *(const float4*)&Klt[d * 128 + tn * 8 + 4];
        float av[8] = {a0.x, a0.y, a0.z, a0.w, a1.x, a1.y, a1.z, a1.w};
        float bv[8] = {b0.x, b0.y, b0.z, b0.w, b1.x, b1.y, b1.z, b1.w};
        #pragma unroll
        for (int i = 0; i < 8; i++)
            #pragma unroll
            for (int j = 0; j < 8; j++) acc[i][j] += av[i] * bv[j];
    }
    #pragma unroll
    for (int i = 0; i < 8; i++)
        #pragma unroll
        for (int j = 0; j < 8; j++) S[(tm * 8 + i) * 128 + tn * 8 + j] = acc[i][j];
    __syncthreads();

    int lane = tid & 31, w = tid >> 5;
    for (int rr = 0; rr < 16; rr++) {
        int row = w * 16 + rr;
        float x0 = S[row * 128 + lane],      x1 = S[row * 128 + lane + 32];
        float x2 = S[row * 128 + lane + 64], x3 = S[row * 128 + lane + 96];
        float mx = fmaxf(fmaxf(x0, x1), fmaxf(x2, x3));
        #pragma unroll
        for (int o = 16; o; o >>= 1) mx = fmaxf(mx, __shfl_xor_sync(0xffffffffu, mx, o));
        float e0 = __expf(x0 - mx), e1 = __expf(x1 - mx);
        float e2 = __expf(x2 - mx), e3 = __expf(x3 - mx);
        float s = e0 + e1 + e2 + e3;
        #pragma unroll
        for (int o = 16; o; o >>= 1) s += __shfl_xor_sync(0xffffffffu, s, o);
        float inv = 1.f / s;
        float* o = g_k2 + bh * 16384 + row * 128;
        o[lane] = e0 * inv; o[lane + 32] = e1 * inv; o[lane + 64] = e2 * inv; o[lane + 96] = e3 * inv;
    }
}

// =====================================================================
// V0 = K^T / max(colsum(K))
// =====================================================================
__global__ __launch_bounds__(256) void vinit_kernel()
{
    int bh = blockIdx.x, tid = threadIdx.x;
    const float* K = g_k2 + bh * 16384;
    __shared__ float cs[128];
    __shared__ float sscale;
    if (tid < 128) {
        float s = 0.f;
        for (int r = 0; r < 128; r++) s += K[r * 128 + tid];
        cs[tid] = s;
    }
    __syncthreads();
    if (tid == 0) {
        float m = cs[0];
        for (int i = 1; i < 128; i++) m = fmaxf(m, cs[i]);
        sscale = 1.f / m;
    }
    __syncthreads();
    float scale = sscale;
    for (int f = tid; f < 16384; f += 256) {
        int i = f >> 7, j = f & 127;
        g_Va[bh * 16384 + f] = scale * K[j * 128 + i];
    }
}

// =====================================================================
// batched 128x128 bmm for Newton-Schulz (fp32)
// =====================================================================
__device__ __forceinline__ float* bufsel(int s)
{
    switch (s) {
        case 0: return g_k2; case 1: return g_P; case 2: return g_M1;
        case 3: return g_M2; case 4: return g_Va; default: return g_Vb;
    }
}

__global__ __launch_bounds__(256) void bmm_kernel(int as, int bs, int cs2, int os,
                                                  float alpha, float beta)
{
    float* sm = (float*)dynsm;
    float* Bs = sm;
    float* At = sm + 16384;
    int bh = blockIdx.y, r0 = blockIdx.x * 32, tid = threadIdx.x;
    const float* A  = bufsel(as)  + bh * 16384;
    const float* Bm = bufsel(bs)  + bh * 16384;
    const float* C  = bufsel(cs2) + bh * 16384;
    float* O        = bufsel(os)  + bh * 16384;

    #pragma unroll
    for (int i = 0; i < 16; i++) {
        int f = i * 1024 + tid * 4;
        *(float4*)&Bs[f] = *(const float4*)&Bm[f];
    }
    #pragma unroll
    for (int i = 0; i < 4; i++) {
        int f = i * 1024 + tid * 4; int r = f >> 7, k0 = f & 127;
        float4 t = *(const float4*)&A[(r0 + r) * 128 + k0];
        At[(k0 + 0) * 32 + r] = t.x; At[(k0 + 1) * 32 + r] = t.y;
        At[(k0 + 2) * 32 + r] = t.z; At[(k0 + 3) * 32 + r] = t.w;
    }
    __syncthreads();

    int rb = (tid >> 5) * 4, cb = (tid & 31) * 4;
    float acc[4][4] = {};
    for (int k = 0; k < 128; k++) {
        float a0 = At[k * 32 + rb + 0], a1 = At[k * 32 + rb + 1];
        float a2 = At[k * 32 + rb + 2], a3 = At[k * 32 + rb + 3];
        float4 b = *(const float4*)&Bs[k * 128 + cb];
        acc[0][0] += a0 * b.x; acc[0][1] += a0 * b.y; acc[0][2] += a0 * b.z; acc[0][3] += a0 * b.w;
        acc[1][0] += a1 * b.x; acc[1][1] += a1 * b.y; acc[1][2] += a1 * b.z; acc[1][3] += a1 * b.w;
        acc[2][0] += a2 * b.x; acc[2][1] += a2 * b.y; acc[2][2] += a2 * b.z; acc[2][3] += a2 * b.w;
        acc[3][0] += a3 * b.x; acc[3][1] += a3 * b.y; acc[3][2] += a3 * b.z; acc[3][3] += a3 * b.w;
    }
    #pragma unroll
    for (int i = 0; i < 4; i++)
        #pragma unroll
        for (int j = 0; j < 4; j++) {
            int idx = (r0 + rb + i) * 128 + cb + j;
            O[idx] = alpha * acc[i][j] + beta * C[idx];
        }
}

// =====================================================================
// k3v: partial C[m=128][d=64] = softmax(k3)_split @ v_split (mma, split-K 4)
// smem per stage: Ah 0 | Al 18432 | Bh 36864 | Bl 46080 ; stage 55296; x2
// dyn smem 110592
// =====================================================================
#define KV_STG 55296

__global__ __launch_bounds__(256) void k3v_mma_kernel()
{
    char* sm = dynsm;
    const uint32_t sb = smem_to_u32(sm);
    int s = blockIdx.x, bh = blockIdx.y, tid = threadIdx.x;
    int lane = tid & 31, w = tid >> 5;
    int wm = w >> 1, wn = w & 1;
    const size_t abase = (size_t)bh * M_ * L_;
    const size_t vbase = (size_t)bh * L_ * D_;

    float acc[2][4][4];
    #pragma unroll
    for (int i = 0; i < 2; i++)
        #pragma unroll
        for (int j = 0; j < 4; j++)
            #pragma unroll
            for (int t = 0; t < 4; t++) acc[i][j][t] = 0.f;

    auto load = [&](int ck, int buf) {
        int k0 = s * 1024 + ck * 64;
        uint32_t S = sb + buf * KV_STG;
        #pragma unroll
        for (int i = 0; i < 8; i++) {               // A: scores split, 128 rows x 128B x2
            int q = tid + i * 256;
            int arr = q >> 10, row = (q >> 3) & 127, c8 = q & 7;
            uint32_t dst = S + arr * 18432 + (uint32_t)(row * 144 + c8 * 16);
            const __nv_bfloat16* src = (arr ? g_s3l : g_s3h) + abase + (size_t)row * L_ + k0 + c8 * 8;
            CP_ASYNC16(dst, src);
        }
        #pragma unroll
        for (int i = 0; i < 4; i++) {               // B: v split, 64 rows x 128B x2
            int q = tid + i * 256;
            int arr = q >> 9, row = (q >> 3) & 63, c8 = q & 7;
            uint32_t dst = S + 36864 + arr * 9216 + (uint32_t)(row * 144 + c8 * 16);
            const __nv_bfloat16* src = (arr ? g_vl : g_vh) + vbase + (size_t)(k0 + row) * D_ + c8 * 8;
            CP_ASYNC16(dst, src);
        }
        CP_COMMIT();
    };

    auto compute = [&](int buf) {
        uint32_t S = sb + buf * KV_STG;
        #pragma unroll
        for (int k16 = 0; k16 < 4; k16++) {
            uint32_t af[2][2][4];
            #pragma unroll
            for (int term = 0; term < 2; term++)
                #pragma unroll
                for (int mt = 0; mt < 2; mt++) {
                    uint32_t addr = S + term * 18432
                        + (uint32_t)((wm * 32 + mt * 16 + (lane & 15)) * 144)
                        + (uint32_t)(k16 * 32) + (uint32_t)((lane >> 4) * 16);
                    ldsm4(af[term][mt], addr);
                }
            uint32_t bf[2][2][4];
            #pragma unroll
            for (int term = 0; term < 2; term++)
                #pragma unroll
                for (int np = 0; np < 2; np++) {
                    uint32_t addr = S + 36864 + term * 9216
                        + (uint32_t)((k16 * 16 + (lane & 15)) * 144)
                        + (uint32_t)((wn * 32 + np * 16 + (lane >> 4) * 8) * 2);
                    ldsm4t(bf[term][np], addr);
                }
            #pragma unroll
            for (int mt = 0; mt < 2; mt++)
                #pragma unroll
                for (int nt = 0; nt < 4; nt++) {
                    float* d = acc[mt][nt];
                    const uint32_t* bh_ = &bf[0][nt >> 1][(nt & 1) * 2];
                    const uint32_t* bl_ = &bf[1][nt >> 1][(nt & 1) * 2];
                    mma16816(d, af[0][mt], bh_);
                    mma16816(d, af[0][mt], bl_);
                    mma16816(d, af[1][mt], bh_);
                }
        }
    };

    load(0, 0);
    #pragma unroll 1
    for (int ck = 0; ck < 16; ck++) {
        if (ck + 1 < 16) {
            load(ck + 1, (ck + 1) & 1);
            CP_WAIT(1);
        } else {
            CP_WAIT(0);
        }
        __syncthreads();
        compute(ck & 1);
        __syncthreads();
    }

    #pragma unroll
    for (int mt = 0; mt < 2; mt++)
        #pragma unroll
        for (int nt = 0; nt < 4; nt++)
            #pragma unroll
            for (int half = 0; half < 2; half++) {
                int m_r = wm * 32 + mt * 16 + (lane >> 2) + half * 8;
                int d_c = wn * 32 + nt * 8 + (lane & 3) * 2;
                float2 t = {acc[mt][nt][half * 2 + 0], acc[mt][nt][half * 2 + 1]};
                *(float2*)&g_k3v_part[((size_t)(s * 64 + bh) * 128 + m_r) * 64 + d_c] = t;
            }
}

__global__ void k3v_reduce_kernel()
{
    int idx = blockIdx.x * blockDim.x + threadIdx.x;  // 524288
    float s = 0.f;
    #pragma unroll
    for (int p = 0; p < 4; p++) s += g_k3v_part[(size_t)p * 524288 + idx];
    g_k3v[idx] = s;
}

// =====================================================================
// y2 = inv(g_Va) @ k3v per head (fp32); epilogue emits y2^T split bf16
// =====================================================================
__global__ __launch_bounds__(256) void y2_kernel()
{
    float* sm = (float*)dynsm;
    float* At = sm;
    float* Bs = sm + 16384;
    int bh = blockIdx.x, tid = threadIdx.x;
    const float* inv = g_Va + bh * 16384;
    const float* kv  = g_k3v + bh * 8192;

    #pragma unroll
    for (int i = 0; i < 16; i++) {
        int f = i * 1024 + tid * 4; int r = f >> 7, k0 = f & 127;
        float4 t = *(const float4*)&inv[f];
        At[(k0 + 0) * 128 + r] = t.x; At[(k0 + 1) * 128 + r] = t.y;
        At[(k0 + 2) * 128 + r] = t.z; At[(k0 + 3) * 128 + r] = t.w;
    }
    #pragma unroll
    for (int i = 0; i < 8; i++) {
        int f = i * 1024 + tid * 4;
        *(float4*)&Bs[f] = *(const float4*)&kv[f];
    }
    __syncthreads();

    int rt = tid >> 4, ct = tid & 15;
    float acc[8][4] = {};
    for (int k = 0; k < 128; k++) {
        float4 a0 = *(const float4*)&At[k * 128 + rt * 8];
        float4 a1 = *(const float4*)&At[k * 128 + rt * 8 + 4];
        float4 b  = *(const float4*)&Bs[k * 64 + ct * 4];
        float av[8] = {a0.x, a0.y, a0.z, a0.w, a1.x, a1.y, a1.z, a1.w};
        #pragma unroll
        for (int i = 0; i < 8; i++) {
            acc[i][0] += av[i] * b.x; acc[i][1] += av[i] * b.y;
            acc[i][2] += av[i] * b.z; acc[i][3] += av[i] * b.w;
        }
    }
    // transposed split store: y2t[bh][d][m]
    #pragma unroll
    for (int i = 0; i < 8; i++)
        #pragma unroll
        for (int j = 0; j < 4; j++) {
            __nv_bfloat16 h, l; split_bf16(acc[i][j], h, l);
            size_t o = (size_t)bh * 8192 + (ct * 4 + j) * 128 + rt * 8 + i;
            g_y2th[o] = h;
            g_y2tl[o] = l;
        }
}

// =====================================================================
// x1: C[l=128][d=64] = kernel1_split @ y2t_split (mma) -> g_ah/g_al split
// smem: Ah 0 | Al 34816 | Bh 69632 | Bl 87040 ; dyn smem 104448 (pitch 272 B)
// =====================================================================
__global__ __launch_bounds__(256) void x1_mma_kernel()
{
    char* sm = dynsm;
    const uint32_t sb = smem_to_u32(sm);
    int bh = blockIdx.y, l0 = blockIdx.x * 128, tid = threadIdx.x;
    int lane = tid & 31, w = tid >> 5;
    int wm = w >> 1, wn = w & 1;

    {
        const __nv_bfloat16* ah = g_k1h + ((size_t)bh * L_ + l0) * 128;
        const __nv_bfloat16* al = g_k1l + ((size_t)bh * L_ + l0) * 128;
        #pragma unroll
        for (int i = 0; i < 16; i++) {
            int q = tid + i * 256;                 // 0..4095
            int arr = q >> 11, row = (q >> 4) & 127, c16 = q & 15;
            uint32_t so = (uint32_t)(arr * 34816 + row * 272 + c16 * 16);
            const __nv_bfloat16* src = (arr ? al : ah) + (size_t)row * 128 + c16 * 8;
            *(uint4*)(sm + so) = *(const uint4*)src;
        }
        const __nv_bfloat16* bhp = g_y2th + (size_t)bh * 8192;
        const __nv_bfloat16* blp = g_y2tl + (size_t)bh * 8192;
        #pragma unroll
        for (int i = 0; i < 8; i++) {
            int q = tid + i * 256;                 // 0..2047
            int arr = q >> 10, row = (q >> 4) & 63, c16 = q & 15;
            uint32_t so = (uint32_t)(69632 + arr * 17408 + row * 272 + c16 * 16);
            const __nv_bfloat16* src = (arr ? blp : bhp) + (size_t)row * 128 + c16 * 8;
            *(uint4*)(sm + so) = *(const uint4*)src;
        }
    }
    __syncthreads();

    float acc[2][4][4];
    #pragma unroll
    for (int i = 0; i < 2; i++)
        #pragma unroll
        for (int j = 0; j < 4; j++)
            #pragma unroll
            for (int t = 0; t < 4; t++) acc[i][j][t] = 0.f;

    #pragma unroll
    for (int k16 = 0; k16 < 8; k16++) {
        uint32_t af[2][2][4];
        #pragma unroll
        for (int term = 0; term < 2; term++)
            #pragma unroll
            for (int mt = 0; mt < 2; mt++) {
                uint32_t addr = sb + term * 34816
                    + (uint32_t)((wm * 32 + mt * 16 + (lane & 15)) * 272)
                    + (uint32_t)(k16 * 32) + (uint32_t)((lane >> 4) * 16);
                ldsm4(af[term][mt], addr);
            }
        uint32_t bf[2][2][4];
        #pragma unroll
        for (int term = 0; term < 2; term++)
            #pragma unroll
            for (int np = 0; np < 2; np++) {
                uint32_t nrow = (uint32_t)(wn * 32 + np * 16 + ((lane >> 4) * 8) + (lane & 7));
                uint32_t addr = sb + 69632 + term * 17408 + nrow * 272
                    + (uint32_t)(k16 * 32) + (uint32_t)(((lane >> 3) & 1) * 16);
                ldsm4(bf[term][np], addr);
            }
        #pragma unroll
        for (int mt = 0; mt < 2; mt++)
            #pragma unroll
            for (int nt = 0; nt < 4; nt++) {
                float* d = acc[mt][nt];
                const uint32_t* bh_ = &bf[0][nt >> 1][(nt & 1) * 2];
                const uint32_t* bl_ = &bf[1][nt >> 1][(nt & 1) * 2];
                mma16816(d, af[0][mt], bh_);
                mma16816(d, af[0][mt], bl_);
                mma16816(d, af[1][mt], bh_);
            }
    }

    int b = bh >> 4, h = bh & 15;
    #pragma unroll
    for (int mt = 0; mt < 2; mt++)
        #pragma unroll
        for (int nt = 0; nt < 4; nt++)
            #pragma unroll
            for (int half = 0; half < 2; half++) {
                int l = l0 + wm * 32 + mt * 16 + (lane >> 2) + half * 8;
                int d_c = wn * 32 + nt * 8 + (lane & 3) * 2;
                size_t o = ((size_t)(b * L_ + l)) * DM_ + h * 64 + d_c;
                __nv_bfloat16 hp[2], lp[2];
                split_bf16(acc[mt][nt][half * 2 + 0], hp[0], lp[0]);
                split_bf16(acc[mt][nt][half * 2 + 1], hp[1], lp[1]);
                *(uint32_t*)&g_ah[o] = *(uint32_t*)hp;
                *(uint32_t*)&g_al[o] = *(uint32_t*)lp;
            }
}

// =====================================================================
// launch
// =====================================================================
extern "C" void kernel_launch(void* const* d_in, const int* in_sizes, int n_in,
                              void* d_out, int out_size)
{
    const float* queries = (const float*)d_in[0];
    const float* keys    = (const float*)d_in[1];
    const float* values  = (const float*)d_in[2];
    const float* Wq = (const float*)d_in[3];
    const float* bq = (const float*)d_in[4];
    const float* Wk = (const float*)d_in[5];
    const float* bk = (const float*)d_in[6];
    const float* Wv = (const float*)d_in[7];
    const float* bv = (const float*)d_in[8];
    const float* Wo = (const float*)d_in[9];
    const float* bo = (const float*)d_in[10];
    float* out = (float*)d_out;

    cudaFuncSetAttribute(gemm_mma_kernel,    cudaFuncAttributeMaxDynamicSharedMemorySize, 81920);
    cudaFuncSetAttribute(k1_mma_kernel,      cudaFuncAttributeMaxDynamicSharedMemorySize, 73728);
    cudaFuncSetAttribute(k3score_mma_kernel, cudaFuncAttributeMaxDynamicSharedMemorySize, 73728);
    cudaFuncSetAttribute(k3v_mma_kernel,     cudaFuncAttributeMaxDynamicSharedMemorySize, 110592);
    cudaFuncSetAttribute(x1_mma_kernel,      cudaFuncAttributeMaxDynamicSharedMemorySize, 104448);
    cudaFuncSetAttribute(k2_kernel,          cudaFuncAttributeMaxDynamicSharedMemorySize, 131072);
    cudaFuncSetAttribute(bmm_kernel,         cudaFuncAttributeMaxDynamicSharedMemorySize, 81920);
    cudaFuncSetAttribute(y2_kernel,          cudaFuncAttributeMaxDynamicSharedMemorySize, 98304);

    __nv_bfloat16 *ahp = nullptr, *alp = nullptr;
    cudaGetSymbolAddress((void**)&ahp, g_ah);
    cudaGetSymbolAddress((void**)&alp, g_al);

    dim3 wt_grid(32, 32), wt_blk(32, 8);
    dim3 gemm_grid(8, 128);

    // projections -> split bf16 q/k/v
    conv_wt_kernel<<<wt_grid, wt_blk>>>(Wq);
    conv_act_kernel<<<16384, 256>>>(queries);
    gemm_mma_kernel<<<gemm_grid, 256, 81920>>>(ahp, alp, bq, nullptr, 0);
    conv_wt_kernel<<<wt_grid, wt_blk>>>(Wk);
    conv_act_kernel<<<16384, 256>>>(keys);
    gemm_mma_kernel<<<gemm_grid, 256, 81920>>>(ahp, alp, bk, nullptr, 1);
    conv_wt_kernel<<<wt_grid, wt_blk>>>(Wv);
    conv_act_kernel<<<16384, 256>>>(values);
    gemm_mma_kernel<<<gemm_grid, 256, 81920>>>(ahp, alp, bv, nullptr, 2);

    // landmarks
    pool_kernel<<<2048, 256>>>();

    // kernel_1 (tensor-core, fused softmax)
    k1_mma_kernel<<<dim3(32, 64), 256, 73728>>>();

    // kernel_3 scores (tensor-core) + softmax -> split
    k3score_mma_kernel<<<dim3(32, 64), 256, 73728>>>();
    softmax4096_kernel<<<8192, 256>>>();

    // kernel_2 + Newton-Schulz (fp32)
    k2_kernel<<<64, 256, 131072>>>();
    vinit_kernel<<<64, 256>>>();
    int cur = 4, nxt = 5;
    for (int it = 0; it < 6; it++) {
        bmm_kernel<<<dim3(4, 64), 256, 81920>>>(0,   cur, 0,   1,   1.0f,  0.0f);
        bmm_kernel<<<dim3(4, 64), 256, 81920>>>(1,   1,   1,   2,  -1.0f,  7.0f);
        bmm_kernel<<<dim3(4, 64), 256, 81920>>>(1,   2,   1,   3,  -1.0f, 15.0f);
        bmm_kernel<<<dim3(4, 64), 256, 81920>>>(cur, 3,   cur, nxt, -0.25f, 3.25f);
        int t = cur; cur = nxt; nxt = t;
    }
    // cur == 4 (g_Va) holds the pseudo-inverse

    // kernel_3 @ v (tensor-core, split-K 4)
    k3v_mma_kernel<<<dim3(4, 64), 256, 110592>>>();
    k3v_reduce_kernel<<<2048, 256>>>();

    // y2 (fp32 + transposed split epilogue), x1 (tensor-core) -> g_ah/g_al
    y2_kernel<<<64, 256, 98304>>>();
    x1_mma_kernel<<<dim3(32, 64), 256, 104448>>>();

    // output projection
    conv_wt_kernel<<<wt_grid, wt_blk>>>(Wo);
    gemm_mma_kernel<<<gemm_grid, 256, 81920>>>(ahp, alp, bo, out, 3);
}